// round 12
// baseline (speedup 1.0000x reference)
#include <cuda_runtime.h>
#include <cuda_bf16.h>
#include <math.h>

#define Bz   4
#define LQ   1024
#define Cc   256
#define Hh   8
#define DH   32
#define DFF  1024
#define LSRC 21760
#define MROWS (Bz*LQ)        // 4096
#define VROWS (Bz*LSRC)      // 87040

// ---------------- scratch (static device globals) ---------------------------
__device__ float g_qk  [MROWS*Cc];
__device__ float g_qk2 [MROWS*Cc];
__device__ float g_qkv [3*MROWS*Cc];
__device__ float g_attn[MROWS*Cc];
__device__ float g_tmp [MROWS*Cc];
__device__ float g_tgt1[MROWS*Cc];
__device__ float g_tgt2[MROWS*Cc];
__device__ float g_off [MROWS*Cc];
__device__ float g_aw  [MROWS*128];
__device__ float g_val [VROWS*Cc];
__device__ float g_ffn [MROWS*DFF];
__device__ float g_part[4*MROWS*Cc];
__device__ float g_ml  [2*MROWS*Hh*2];
__device__ float g_zero[DFF];          // zero-initialized

__device__ __forceinline__ unsigned rna_tf32(float x) {
    unsigned r;
    asm("cvt.rna.tf32.f32 %0, %1;" : "=r"(r) : "f"(x));
    return r;
}

#define MMA_TF32(C, A0,A1,A2,A3, B0,B1) \
    asm volatile("mma.sync.aligned.m16n8k8.row.col.f32.tf32.tf32.f32 " \
                 "{%0,%1,%2,%3}, {%4,%5,%6,%7}, {%8,%9}, {%0,%1,%2,%3};" \
                 : "+f"(C[0]), "+f"(C[1]), "+f"(C[2]), "+f"(C[3]) \
                 : "r"(A0), "r"(A1), "r"(A2), "r"(A3), "r"(B0), "r"(B1))

// ---------------- elementwise add ------------------------------------------
__global__ void add_kernel(const float* __restrict__ a, const float* __restrict__ b,
                           float* __restrict__ y, int n)
{
    int i = blockIdx.x * 256 + threadIdx.x;
    if (i < n) y[i] = a[i] + b[i];
}

// ---------------- tf32 tensor-core GEMM, NSTG-stage cp.async pipeline -------
// Y[M,N] = X[M,K(ldx)] @ W[N,K(ldw)]^T + bias. Block tile BM x BN, 256 thr
// (8 warps 2x4); warp tile BM/2 x BN/4. Raw fp32 bits as tf32 operands.
// mode 0: plain. mode 1: QKV batch over z. mode 2: off/aw pair.
// mode 3: split-K over z (X,W advance z*K cols; bias z>0 -> zeros; Y partials).
#define GP 36
template<int K, int BM, int BN, int NSTG>
__global__ __launch_bounds__(256, 2)
void gemm_tc(const float* __restrict__ X, const float* __restrict__ Xalt,
             const float* __restrict__ W, const float* __restrict__ bias,
             float* __restrict__ Y, int M, int N, int relu, int mode,
             const float* __restrict__ W2, const float* __restrict__ b2,
             float* __restrict__ Y2, int N2, int ldx, int ldw)
{
    extern __shared__ float smem[];
    constexpr int MT = BM / 32;
    constexpr int NT = BN / 32;
    constexpr int XTILE_F = BM * GP;
    constexpr int STAGE = (BM + BN) * GP;
    constexpr int NS = K >> 5;
    constexpr int TPRX = 256 / BM;
    constexpr int XG   = (32 / TPRX) / 4;
    constexpr int TPRW = 256 / BN;
    constexpr int WG   = (32 / TPRW) / 4;

    const int z = blockIdx.z;
    if (mode == 1 && z) {
        W    += (size_t)z * 256 * K;
        bias += z * 256;
        Y    += (size_t)z * M * N;
        if (z == 2) X = Xalt;
    } else if (mode == 2 && z) {
        if (blockIdx.x >= 2) return;
        W = W2; bias = b2; Y = Y2; N = N2;
    } else if (mode == 3) {
        X += z * K;
        W += z * K;
        Y += (size_t)z * M * N;
        if (z) bias = b2;
    }

    const int t    = threadIdx.x;
    const int warp = t >> 5;
    const int lane = t & 31;
    const int g    = lane >> 2;
    const int tg   = lane & 3;
    const int warp_m = warp >> 2;
    const int warp_n = warp & 3;
    const int m0 = blockIdx.y * BM;
    const int n0 = blockIdx.x * BN;

    const int xrow = t / TPRX;
    const int xcol = (t % TPRX) * (32 / TPRX);
    const int wrow = t / TPRW;
    const int wcol = (t % TPRW) * (32 / TPRW);

    float c[MT][NT][4];
#pragma unroll
    for (int i = 0; i < MT; i++)
#pragma unroll
        for (int j = 0; j < NT; j++)
#pragma unroll
            for (int r = 0; r < 4; r++) c[i][j][r] = 0.f;

    auto prefetch = [&](int s) {
        const int k0 = s << 5;
        float* xs = smem + (s % NSTG) * STAGE;
        float* ws = xs + XTILE_F;
        const float* gx = &X[(size_t)(m0 + xrow) * ldx + k0 + xcol];
        unsigned sx = (unsigned)__cvta_generic_to_shared(&xs[xrow * GP + xcol]);
#pragma unroll
        for (int q = 0; q < XG; q++)
            asm volatile("cp.async.cg.shared.global [%0], [%1], 16;\n"
                         :: "r"(sx + q * 16), "l"(gx + q * 4));
        const float* gw = &W[(size_t)(n0 + wrow) * ldw + k0 + wcol];
        unsigned sw = (unsigned)__cvta_generic_to_shared(&ws[wrow * GP + wcol]);
#pragma unroll
        for (int q = 0; q < WG; q++)
            asm volatile("cp.async.cg.shared.global [%0], [%1], 16;\n"
                         :: "r"(sw + q * 16), "l"(gw + q * 4));
        asm volatile("cp.async.commit_group;\n");
    };

#pragma unroll
    for (int i = 0; i < NSTG - 1; i++) prefetch(i);

#pragma unroll
    for (int s = 0; s < NS; s++) {
        if constexpr (NSTG == 2) {
            asm volatile("cp.async.wait_group 0;\n");
        } else {  // NSTG == 3
            if (s < NS - 1) asm volatile("cp.async.wait_group 1;\n");
            else            asm volatile("cp.async.wait_group 0;\n");
        }
        __syncthreads();                      // all warps done with reused buf
        if (s + NSTG - 1 < NS) prefetch(s + NSTG - 1);

        const float* xs = smem + (s % NSTG) * STAGE;
        const float* ws = xs + XTILE_F;

#pragma unroll
        for (int ks = 0; ks < 4; ks++) {
            const int kk = ks * 8;
            unsigned a[MT][4], b[NT][2];
#pragma unroll
            for (int mt = 0; mt < MT; mt++) {
                int rb = warp_m * (BM / 2) + mt * 16;
                a[mt][0] = __float_as_uint(xs[(rb + g    ) * GP + kk + tg    ]);
                a[mt][1] = __float_as_uint(xs[(rb + g + 8) * GP + kk + tg    ]);
                a[mt][2] = __float_as_uint(xs[(rb + g    ) * GP + kk + tg + 4]);
                a[mt][3] = __float_as_uint(xs[(rb + g + 8) * GP + kk + tg + 4]);
            }
#pragma unroll
            for (int nt = 0; nt < NT; nt++) {
                int nb = warp_n * (BN / 4) + nt * 8 + g;
                b[nt][0] = __float_as_uint(ws[nb * GP + kk + tg    ]);
                b[nt][1] = __float_as_uint(ws[nb * GP + kk + tg + 4]);
            }
#pragma unroll
            for (int mt = 0; mt < MT; mt++)
#pragma unroll
                for (int nt = 0; nt < NT; nt++)
                    MMA_TF32(c[mt][nt], a[mt][0], a[mt][1], a[mt][2], a[mt][3],
                             b[nt][0], b[nt][1]);
        }
    }

#pragma unroll
    for (int mt = 0; mt < MT; mt++) {
#pragma unroll
        for (int nt = 0; nt < NT; nt++) {
            int col = n0 + warp_n * (BN / 4) + nt * 8 + 2 * tg;
            float b0 = bias[col], b1 = bias[col + 1];
            int r0 = m0 + warp_m * (BM / 2) + mt * 16 + g;
            float v0 = c[mt][nt][0] + b0;
            float v1 = c[mt][nt][1] + b1;
            float v2 = c[mt][nt][2] + b0;
            float v3 = c[mt][nt][3] + b1;
            if (relu) {
                v0 = fmaxf(v0, 0.f); v1 = fmaxf(v1, 0.f);
                v2 = fmaxf(v2, 0.f); v3 = fmaxf(v3, 0.f);
            }
            Y[(size_t)r0 * N + col]           = v0;
            Y[(size_t)r0 * N + col + 1]       = v1;
            Y[(size_t)(r0 + 8) * N + col]     = v2;
            Y[(size_t)(r0 + 8) * N + col + 1] = v3;
        }
    }
}

#define SMEMB(BM,BN,NSTG) ((NSTG) * ((BM) + (BN)) * GP * 4)

// ---------------- residual + LayerNorm (row = 256) --------------------------
__global__ void add_ln_kernel(const float* __restrict__ A, const float* __restrict__ Bv,
                              const float* __restrict__ g, const float* __restrict__ be,
                              const float* __restrict__ qpos,
                              float* __restrict__ Y, float* __restrict__ Yq)
{
    int row = blockIdx.x, t = threadIdx.x;
    float x = A[(size_t)row * Cc + t] + Bv[(size_t)row * Cc + t];
    float s = x, s2 = x * x;
#pragma unroll
    for (int o = 16; o > 0; o >>= 1) {
        s  += __shfl_xor_sync(0xffffffffu, s, o);
        s2 += __shfl_xor_sync(0xffffffffu, s2, o);
    }
    __shared__ float ss[8], ss2[8];
    int w = t >> 5;
    if ((t & 31) == 0) { ss[w] = s; ss2[w] = s2; }
    __syncthreads();
    s = 0.f; s2 = 0.f;
#pragma unroll
    for (int i = 0; i < 8; i++) { s += ss[i]; s2 += ss2[i]; }
    float mean = s * (1.f / Cc);
    float var  = s2 * (1.f / Cc) - mean * mean;
    float inv  = rsqrtf(var + 1e-5f);
    float y = (x - mean) * inv * g[t] + be[t];
    Y[(size_t)row * Cc + t] = y;
    if (qpos) Yq[(size_t)row * Cc + t] = y + qpos[(size_t)row * Cc + t];
}

// residual + 4 split-K partials + LayerNorm
__global__ void add_ln4_kernel(const float* __restrict__ A, const float* __restrict__ P,
                               const float* __restrict__ g, const float* __restrict__ be,
                               float* __restrict__ Y)
{
    int row = blockIdx.x, t = threadIdx.x;
    size_t idx = (size_t)row * Cc + t;
    float x = A[idx] + P[idx] + P[idx + (size_t)MROWS*Cc]
            + P[idx + (size_t)2*MROWS*Cc] + P[idx + (size_t)3*MROWS*Cc];
    float s = x, s2 = x * x;
#pragma unroll
    for (int o = 16; o > 0; o >>= 1) {
        s  += __shfl_xor_sync(0xffffffffu, s, o);
        s2 += __shfl_xor_sync(0xffffffffu, s2, o);
    }
    __shared__ float ss[8], ss2[8];
    int w = t >> 5;
    if ((t & 31) == 0) { ss[w] = s; ss2[w] = s2; }
    __syncthreads();
    s = 0.f; s2 = 0.f;
#pragma unroll
    for (int i = 0; i < 8; i++) { s += ss[i]; s2 += ss2[i]; }
    float mean = s * (1.f / Cc);
    float var  = s2 * (1.f / Cc) - mean * mean;
    float inv  = rsqrtf(var + 1e-5f);
    Y[idx] = (x - mean) * inv * g[t] + be[t];
}

// ---------------- tensor-core flash attention, split-KV over z --------------
// grid (LQ/128, B*H, 2). CTA z handles keys [z*512, z*512+512). Writes raw
// (unnormalized) accumulator to P[z] and per-row (m, l) to ml.
#define KP 36
#define VP 68
__global__ __launch_bounds__(256, 2)
void attn_kernel(const float* __restrict__ Q, const float* __restrict__ K,
                 const float* __restrict__ V, float* __restrict__ P,
                 float* __restrict__ ml)
{
    __shared__ float Qs[128 * KP];
    __shared__ float Ks[64 * KP];
    __shared__ float Vt[32 * VP];

    const int t = threadIdx.x;
    const int warp = t >> 5, lane = t & 31;
    const int g = lane >> 2, tg = lane & 3;
    const int bh = blockIdx.y;
    const int b = bh >> 3, h = bh & 7;
    const int z = blockIdx.z;
    const int q0 = blockIdx.x * 128;
    const size_t base = ((size_t)b * LQ) * Cc + h * DH;

#pragma unroll
    for (int j = 0; j < 4; j++) {
        int idx = j * 256 + t;
        int row = idx >> 3, c4 = (idx & 7) * 4;
        float4 v4 = *(const float4*)&Q[base + (size_t)(q0 + row) * Cc + c4];
        v4.x *= 0.17677669529663687f; v4.y *= 0.17677669529663687f;
        v4.z *= 0.17677669529663687f; v4.w *= 0.17677669529663687f;
        *(float4*)&Qs[row * KP + c4] = v4;
    }
    __syncthreads();

    unsigned qa[4][4];
    {
        int r = warp * 16 + g;
#pragma unroll
        for (int kt = 0; kt < 4; kt++) {
            qa[kt][0] = __float_as_uint(Qs[r * KP + kt * 8 + tg]);
            qa[kt][1] = __float_as_uint(Qs[(r + 8) * KP + kt * 8 + tg]);
            qa[kt][2] = __float_as_uint(Qs[r * KP + kt * 8 + tg + 4]);
            qa[kt][3] = __float_as_uint(Qs[(r + 8) * KP + kt * 8 + tg + 4]);
        }
    }

    float o[4][4];
#pragma unroll
    for (int nt = 0; nt < 4; nt++)
#pragma unroll
        for (int r = 0; r < 4; r++) o[nt][r] = 0.f;
    float m0 = -1e30f, m1 = -1e30f, l0 = 0.f, l1 = 0.f;

    const int cbeg = z * 512;
    for (int c0 = cbeg; c0 < cbeg + 512; c0 += 64) {
        __syncthreads();
#pragma unroll
        for (int j = 0; j < 2; j++) {
            int idx = j * 256 + t;
            int row = idx >> 3, c4 = (idx & 7) * 4;
            *(float4*)&Ks[row * KP + c4] =
                *(const float4*)&K[base + (size_t)(c0 + row) * Cc + c4];
        }
        {
            int key = t & 63, dg = t >> 6;
#pragma unroll
            for (int jj = 0; jj < 2; jj++) {
                float4 v4 = *(const float4*)&V[base + (size_t)(c0 + key) * Cc + dg * 8 + jj * 4];
                Vt[(dg * 8 + jj * 4 + 0) * VP + key] = __uint_as_float(rna_tf32(v4.x));
                Vt[(dg * 8 + jj * 4 + 1) * VP + key] = __uint_as_float(rna_tf32(v4.y));
                Vt[(dg * 8 + jj * 4 + 2) * VP + key] = __uint_as_float(rna_tf32(v4.z));
                Vt[(dg * 8 + jj * 4 + 3) * VP + key] = __uint_as_float(rna_tf32(v4.w));
            }
        }
        __syncthreads();

        float c[8][4];
#pragma unroll
        for (int nt = 0; nt < 8; nt++)
#pragma unroll
            for (int r = 0; r < 4; r++) c[nt][r] = 0.f;
#pragma unroll
        for (int kt = 0; kt < 4; kt++) {
#pragma unroll
            for (int nt = 0; nt < 8; nt++) {
                unsigned b0 = __float_as_uint(Ks[(nt * 8 + g) * KP + kt * 8 + tg]);
                unsigned b1 = __float_as_uint(Ks[(nt * 8 + g) * KP + kt * 8 + tg + 4]);
                MMA_TF32(c[nt], qa[kt][0], qa[kt][1], qa[kt][2], qa[kt][3], b0, b1);
            }
        }

        float mx0 = -1e30f, mx1 = -1e30f;
#pragma unroll
        for (int nt = 0; nt < 8; nt++) {
            mx0 = fmaxf(mx0, fmaxf(c[nt][0], c[nt][1]));
            mx1 = fmaxf(mx1, fmaxf(c[nt][2], c[nt][3]));
        }
        mx0 = fmaxf(mx0, __shfl_xor_sync(0xffffffffu, mx0, 1));
        mx0 = fmaxf(mx0, __shfl_xor_sync(0xffffffffu, mx0, 2));
        mx1 = fmaxf(mx1, __shfl_xor_sync(0xffffffffu, mx1, 1));
        mx1 = fmaxf(mx1, __shfl_xor_sync(0xffffffffu, mx1, 2));
        float mn0 = fmaxf(m0, mx0), mn1 = fmaxf(m1, mx1);
        float cor0 = __expf(m0 - mn0), cor1 = __expf(m1 - mn1);
        l0 *= cor0; l1 *= cor1;
#pragma unroll
        for (int nt = 0; nt < 4; nt++) {
            o[nt][0] *= cor0; o[nt][1] *= cor0;
            o[nt][2] *= cor1; o[nt][3] *= cor1;
        }
#pragma unroll
        for (int nt = 0; nt < 8; nt++) {
            float p0 = __expf(c[nt][0] - mn0);
            float p1 = __expf(c[nt][1] - mn0);
            float p2 = __expf(c[nt][2] - mn1);
            float p3 = __expf(c[nt][3] - mn1);
            l0 += p0 + p1; l1 += p2 + p3;
            c[nt][0] = __uint_as_float(rna_tf32(p0));
            c[nt][1] = __uint_as_float(rna_tf32(p1));
            c[nt][2] = __uint_as_float(rna_tf32(p2));
            c[nt][3] = __uint_as_float(rna_tf32(p3));
        }
        m0 = mn0; m1 = mn1;

        const int src0 = (lane & ~3) | (tg >> 1);
        const int src2 = src0 + 2;
        const bool odd = tg & 1;
#pragma unroll
        for (int kt = 0; kt < 8; kt++) {
            float e00 = __shfl_sync(0xffffffffu, c[kt][0], src0);
            float e01 = __shfl_sync(0xffffffffu, c[kt][1], src0);
            float e10 = __shfl_sync(0xffffffffu, c[kt][2], src0);
            float e11 = __shfl_sync(0xffffffffu, c[kt][3], src0);
            float e20 = __shfl_sync(0xffffffffu, c[kt][0], src2);
            float e21 = __shfl_sync(0xffffffffu, c[kt][1], src2);
            float e30 = __shfl_sync(0xffffffffu, c[kt][2], src2);
            float e31 = __shfl_sync(0xffffffffu, c[kt][3], src2);
            unsigned a0 = __float_as_uint(odd ? e01 : e00);
            unsigned a1 = __float_as_uint(odd ? e11 : e10);
            unsigned a2 = __float_as_uint(odd ? e21 : e20);
            unsigned a3 = __float_as_uint(odd ? e31 : e30);
#pragma unroll
            for (int nt = 0; nt < 4; nt++) {
                unsigned b0 = __float_as_uint(Vt[(nt * 8 + g) * VP + kt * 8 + tg]);
                unsigned b1 = __float_as_uint(Vt[(nt * 8 + g) * VP + kt * 8 + tg + 4]);
                MMA_TF32(o[nt], a0, a1, a2, a3, b0, b1);
            }
        }
    }

    l0 += __shfl_xor_sync(0xffffffffu, l0, 1);
    l0 += __shfl_xor_sync(0xffffffffu, l0, 2);
    l1 += __shfl_xor_sync(0xffffffffu, l1, 1);
    l1 += __shfl_xor_sync(0xffffffffu, l1, 2);

    float* Pz = P + (size_t)z * MROWS * Cc;
    int r0 = q0 + warp * 16 + g;
#pragma unroll
    for (int nt = 0; nt < 4; nt++) {
        int col = nt * 8 + 2 * tg;
        *(float2*)&Pz[base + (size_t)r0 * Cc + col]       = make_float2(o[nt][0], o[nt][1]);
        *(float2*)&Pz[base + (size_t)(r0 + 8) * Cc + col] = make_float2(o[nt][2], o[nt][3]);
    }
    if (tg == 0) {
        int grow0 = b * LQ + r0;
        ml[(((size_t)z * MROWS + grow0) * Hh + h) * 2 + 0] = m0;
        ml[(((size_t)z * MROWS + grow0) * Hh + h) * 2 + 1] = l0;
        ml[(((size_t)z * MROWS + grow0 + 8) * Hh + h) * 2 + 0] = m1;
        ml[(((size_t)z * MROWS + grow0 + 8) * Hh + h) * 2 + 1] = l1;
    }
}

// merge two split-KV partials
__global__ void attn_merge_kernel(const float* __restrict__ P,
                                  const float* __restrict__ ml,
                                  float* __restrict__ O)
{
    int row = blockIdx.x, t = threadIdx.x;
    int h = t >> 5;
    float m0 = ml[((size_t)row * Hh + h) * 2 + 0];
    float l0 = ml[((size_t)row * Hh + h) * 2 + 1];
    float m1 = ml[(((size_t)MROWS + row) * Hh + h) * 2 + 0];
    float l1 = ml[(((size_t)MROWS + row) * Hh + h) * 2 + 1];
    float M = fmaxf(m0, m1);
    float e0 = __expf(m0 - M), e1 = __expf(m1 - M);
    float inv = 1.f / (l0 * e0 + l1 * e1);
    size_t idx = (size_t)row * Cc + t;
    O[idx] = (P[idx] * e0 + P[idx + (size_t)MROWS * Cc] * e1) * inv;
}

// ---------------- deformable sampling (warp per (b,q,h), lane = channel) ----
__global__ void deform_kernel(const float* __restrict__ val, const float* __restrict__ offs,
                              const float* __restrict__ awl, const float* __restrict__ ref,
                              float* __restrict__ out)
{
    const int gid  = blockIdx.x * 4 + (threadIdx.x >> 5);
    const int lane = threadIdx.x & 31;
    const int h   = gid & 7;
    const int row = gid >> 3;
    const int b   = row >> 10;

    float a[16];
    float mx = -1e30f;
#pragma unroll
    for (int i = 0; i < 16; i++) {
        a[i] = awl[(size_t)row * 128 + h * 16 + i];
        mx = fmaxf(mx, a[i]);
    }
    float ssum = 0.f;
#pragma unroll
    for (int i = 0; i < 16; i++) { a[i] = __expf(a[i] - mx); ssum += a[i]; }
    float invs = 1.f / ssum;

    const int starts[4] = {0, 16384, 20480, 21504};
    float acc = 0.f;
#pragma unroll
    for (int lvl = 0; lvl < 4; lvl++) {
        const int Wl = 128 >> lvl;
        const int Hl = 128 >> lvl;
        const int start = starts[lvl];
        float rx = ref[((size_t)row * 4 + lvl) * 2 + 0];
        float ry = ref[((size_t)row * 4 + lvl) * 2 + 1];
#pragma unroll
        for (int p = 0; p < 4; p++) {
            size_t obase = (size_t)row * 256 + (((h * 4 + lvl) * 4 + p) * 2);
            float ox = offs[obase + 0];
            float oy = offs[obase + 1];
            float x = rx * (float)Wl + ox - 0.5f;
            float y = ry * (float)Hl + oy - 0.5f;
            float xf = floorf(x), yf = floorf(y);
            int x0 = (int)xf, y0 = (int)yf;
            float wx1 = x - xf, wx0 = 1.f - wx1;
            float wy1 = y - yf, wy0 = 1.f - wy1;
            float aw = a[lvl * 4 + p] * invs;

            float w00 = wx0 * wy0 * aw, w10 = wx1 * wy0 * aw;
            float w01 = wx0 * wy1 * aw, w11 = wx1 * wy1 * aw;
#pragma unroll
            for (int cidx = 0; cidx < 4; cidx++) {
                int ix = x0 + (cidx & 1);
                int iy = y0 + (cidx >> 1);
                float w = (cidx == 0) ? w00 : (cidx == 1) ? w10 : (cidx == 2) ? w01 : w11;
                if (ix >= 0 && ix < Wl && iy >= 0 && iy < Hl) {
                    size_t idx = (size_t)(b * LSRC + start + iy * Wl + ix) * Cc + h * DH + lane;
                    acc += w * val[idx];
                }
            }
        }
    }
    out[(size_t)row * Cc + h * DH + lane] = acc;
}

// ---------------- launcher ---------------------------------------------------
extern "C" void kernel_launch(void* const* d_in, const int* in_sizes, int n_in,
                              void* d_out, int out_size)
{
    const float* tgt   = (const float*)d_in[0];
    const float* qpos  = (const float*)d_in[1];
    const float* refp  = (const float*)d_in[2];
    const float* src   = (const float*)d_in[3];
    const float* in_w  = (const float*)d_in[4];
    const float* in_b  = (const float*)d_in[5];
    const float* sa_w  = (const float*)d_in[6];
    const float* sa_b  = (const float*)d_in[7];
    const float* off_w = (const float*)d_in[8];
    const float* off_b = (const float*)d_in[9];
    const float* aw_w  = (const float*)d_in[10];
    const float* aw_b  = (const float*)d_in[11];
    const float* val_w = (const float*)d_in[12];
    const float* val_b = (const float*)d_in[13];
    const float* co_w  = (const float*)d_in[14];
    const float* co_b  = (const float*)d_in[15];
    const float* ln1_g = (const float*)d_in[16];
    const float* ln1_b = (const float*)d_in[17];
    const float* ln2_g = (const float*)d_in[18];
    const float* ln2_b = (const float*)d_in[19];
    const float* ln3_g = (const float*)d_in[20];
    const float* ln3_b = (const float*)d_in[21];
    const float* f1_w  = (const float*)d_in[22];
    const float* f1_b  = (const float*)d_in[23];
    const float* f2_w  = (const float*)d_in[24];
    const float* f2_b  = (const float*)d_in[25];
    float* out = (float*)d_out;

    float *qk, *qk2, *qkv, *attn, *tmp, *t1, *t2, *off, *aw, *val, *ffn, *part, *ml, *zero;
    cudaGetSymbolAddress((void**)&qk,   g_qk);
    cudaGetSymbolAddress((void**)&qk2,  g_qk2);
    cudaGetSymbolAddress((void**)&qkv,  g_qkv);
    cudaGetSymbolAddress((void**)&attn, g_attn);
    cudaGetSymbolAddress((void**)&tmp,  g_tmp);
    cudaGetSymbolAddress((void**)&t1,   g_tgt1);
    cudaGetSymbolAddress((void**)&t2,   g_tgt2);
    cudaGetSymbolAddress((void**)&off,  g_off);
    cudaGetSymbolAddress((void**)&aw,   g_aw);
    cudaGetSymbolAddress((void**)&val,  g_val);
    cudaGetSymbolAddress((void**)&ffn,  g_ffn);
    cudaGetSymbolAddress((void**)&part, g_part);
    cudaGetSymbolAddress((void**)&ml,   g_ml);
    cudaGetSymbolAddress((void**)&zero, g_zero);

    static cudaStream_t s1;
    static cudaEvent_t evFork, evJoin;
    static int inited = 0;
    if (!inited) {
        cudaStreamCreateWithFlags(&s1, cudaStreamNonBlocking);
        cudaEventCreateWithFlags(&evFork, cudaEventDisableTiming);
        cudaEventCreateWithFlags(&evJoin, cudaEventDisableTiming);
        cudaFuncSetAttribute(gemm_tc<256,64,64,3>,
                             cudaFuncAttributeMaxDynamicSharedMemorySize, SMEMB(64,64,3));
        cudaFuncSetAttribute(gemm_tc<256,128,64,3>,
                             cudaFuncAttributeMaxDynamicSharedMemorySize, SMEMB(128,64,3));
        cudaFuncSetAttribute(gemm_tc<256,128,128,2>,
                             cudaFuncAttributeMaxDynamicSharedMemorySize, SMEMB(128,128,2));
        inited = 1;
    }

    const int NTOT = MROWS * Cc;

    // 1) qk = tgt + query_pos
    add_kernel<<<(NTOT + 255) / 256, 256>>>(tgt, qpos, qk, NTOT);

    // fork: value projection on side stream (depends only on src)
    cudaEventRecord(evFork, 0);
    cudaStreamWaitEvent(s1, evFork, 0);
    gemm_tc<256,128,128,2><<<dim3(2, VROWS / 128), 256, SMEMB(128,128,2), s1>>>(
        src, nullptr, val_w, val_b, val, VROWS, Cc, 0, 0,
        nullptr, nullptr, nullptr, 0, 256, 256);
    cudaEventRecord(evJoin, s1);

    // 2) Q/K/V projections — batched over grid.z
    gemm_tc<256,64,64,3><<<dim3(4, 64, 3), 256, SMEMB(64,64,3)>>>(
        qk, tgt, in_w, in_b, qkv, MROWS, Cc, 0, 1,
        nullptr, nullptr, nullptr, 0, 256, 256);

    // 3) attention: split-KV (z=2) + merge
    attn_kernel<<<dim3(LQ / 128, Bz * Hh, 2), 256>>>(
        qkv, qkv + MROWS * Cc, qkv + 2 * MROWS * Cc, part, ml);
    attn_merge_kernel<<<MROWS, 256>>>(part, ml, attn);

    // 4) self-attn out proj + residual + LN(ln2) -> t1, and qk2 = t1 + qpos
    gemm_tc<256,64,64,3><<<dim3(4, 64), 256, SMEMB(64,64,3)>>>(
        attn, nullptr, sa_w, sa_b, tmp, MROWS, Cc, 0, 0,
        nullptr, nullptr, nullptr, 0, 256, 256);
    add_ln_kernel<<<MROWS, 256>>>(tgt, tmp, ln2_g, ln2_b, qpos, t1, qk2);

    // 5+6) offsets + attention weights in one z-batched launch
    gemm_tc<256,64,64,3><<<dim3(4, 64, 2), 256, SMEMB(64,64,3)>>>(
        qk2, nullptr, off_w, off_b, off, MROWS, Cc, 0, 2,
        aw_w, aw_b, aw, 128, 256, 256);

    // join value projection, then deformable sampling
    cudaStreamWaitEvent(0, evJoin, 0);
    deform_kernel<<<(MROWS * Hh) / 4, 128>>>(val, off, aw, refp, attn);

    // 8) co proj + residual + LN(ln1) -> t2
    gemm_tc<256,64,64,3><<<dim3(4, 64), 256, SMEMB(64,64,3)>>>(
        attn, nullptr, co_w, co_b, tmp, MROWS, Cc, 0, 0,
        nullptr, nullptr, nullptr, 0, 256, 256);
    add_ln_kernel<<<MROWS, 256>>>(t1, tmp, ln1_g, ln1_b, nullptr, t2, nullptr);

    // 9) FFN: f1 (relu), f2 split-K over z=4, fused reduce+LN
    gemm_tc<256,128,64,3><<<dim3(16, 32), 256, SMEMB(128,64,3)>>>(
        t2, nullptr, f1_w, f1_b, ffn, MROWS, DFF, 1, 0,
        nullptr, nullptr, nullptr, 0, 256, 256);
    gemm_tc<256,64,64,3><<<dim3(4, 64, 4), 256, SMEMB(64,64,3)>>>(
        ffn, nullptr, f2_w, f2_b, part, MROWS, Cc, 0, 3,
        nullptr, zero, nullptr, 0, 1024, 1024);
    add_ln4_kernel<<<MROWS, 256>>>(t2, part, ln3_g, ln3_b, out);
}

// round 13
// speedup vs baseline: 1.0504x; 1.0504x over previous
#include <cuda_runtime.h>
#include <cuda_bf16.h>
#include <math.h>

#define Bz   4
#define LQ   1024
#define Cc   256
#define Hh   8
#define DH   32
#define DFF  1024
#define LSRC 21760
#define MROWS (Bz*LQ)        // 4096
#define VROWS (Bz*LSRC)      // 87040

// ---------------- scratch (static device globals) ---------------------------
__device__ float g_qk  [MROWS*Cc];
__device__ float g_qk2 [MROWS*Cc];
__device__ float g_qkv [3*MROWS*Cc];
__device__ float g_attn[MROWS*Cc];
__device__ float g_tmp [MROWS*Cc];
__device__ float g_tgt1[MROWS*Cc];
__device__ float g_tgt2[MROWS*Cc];
__device__ float g_off [MROWS*Cc];
__device__ float g_aw  [MROWS*128];
__device__ float g_val [VROWS*Cc];
__device__ float g_ffn [MROWS*DFF];
__device__ float g_part[4*MROWS*Cc];
__device__ float g_zero[DFF];          // zero-initialized

__device__ __forceinline__ unsigned rna_tf32(float x) {
    unsigned r;
    asm("cvt.rna.tf32.f32 %0, %1;" : "=r"(r) : "f"(x));
    return r;
}

#define MMA_TF32(C, A0,A1,A2,A3, B0,B1) \
    asm volatile("mma.sync.aligned.m16n8k8.row.col.f32.tf32.tf32.f32 " \
                 "{%0,%1,%2,%3}, {%4,%5,%6,%7}, {%8,%9}, {%0,%1,%2,%3};" \
                 : "+f"(C[0]), "+f"(C[1]), "+f"(C[2]), "+f"(C[3]) \
                 : "r"(A0), "r"(A1), "r"(A2), "r"(A3), "r"(B0), "r"(B1))

// ---------------- elementwise add ------------------------------------------
__global__ void add_kernel(const float* __restrict__ a, const float* __restrict__ b,
                           float* __restrict__ y, int n)
{
    int i = blockIdx.x * 256 + threadIdx.x;
    if (i < n) y[i] = a[i] + b[i];
}

// ---------------- tf32 tensor-core GEMM, NSTG-stage cp.async pipeline -------
#define GP 36
template<int K, int BM, int BN, int NSTG>
__global__ __launch_bounds__(256, 2)
void gemm_tc(const float* __restrict__ X, const float* __restrict__ Xalt,
             const float* __restrict__ W, const float* __restrict__ bias,
             float* __restrict__ Y, int M, int N, int relu, int mode,
             const float* __restrict__ W2, const float* __restrict__ b2,
             float* __restrict__ Y2, int N2, int ldx, int ldw)
{
    extern __shared__ float smem[];
    constexpr int MT = BM / 32;
    constexpr int NT = BN / 32;
    constexpr int XTILE_F = BM * GP;
    constexpr int STAGE = (BM + BN) * GP;
    constexpr int NS = K >> 5;
    constexpr int TPRX = 256 / BM;
    constexpr int XG   = (32 / TPRX) / 4;
    constexpr int TPRW = 256 / BN;
    constexpr int WG   = (32 / TPRW) / 4;

    const int z = blockIdx.z;
    if (mode == 1 && z) {
        W    += (size_t)z * 256 * K;
        bias += z * 256;
        Y    += (size_t)z * M * N;
        if (z == 2) X = Xalt;
    } else if (mode == 2 && z) {
        if (blockIdx.x >= 2) return;
        W = W2; bias = b2; Y = Y2; N = N2;
    } else if (mode == 3) {
        X += z * K;
        W += z * K;
        Y += (size_t)z * M * N;
        if (z) bias = b2;
    }

    const int t    = threadIdx.x;
    const int warp = t >> 5;
    const int lane = t & 31;
    const int g    = lane >> 2;
    const int tg   = lane & 3;
    const int warp_m = warp >> 2;
    const int warp_n = warp & 3;
    const int m0 = blockIdx.y * BM;
    const int n0 = blockIdx.x * BN;

    const int xrow = t / TPRX;
    const int xcol = (t % TPRX) * (32 / TPRX);
    const int wrow = t / TPRW;
    const int wcol = (t % TPRW) * (32 / TPRW);

    float c[MT][NT][4];
#pragma unroll
    for (int i = 0; i < MT; i++)
#pragma unroll
        for (int j = 0; j < NT; j++)
#pragma unroll
            for (int r = 0; r < 4; r++) c[i][j][r] = 0.f;

    auto prefetch = [&](int s) {
        const int k0 = s << 5;
        float* xs = smem + (s % NSTG) * STAGE;
        float* ws = xs + XTILE_F;
        const float* gx = &X[(size_t)(m0 + xrow) * ldx + k0 + xcol];
        unsigned sx = (unsigned)__cvta_generic_to_shared(&xs[xrow * GP + xcol]);
#pragma unroll
        for (int q = 0; q < XG; q++)
            asm volatile("cp.async.cg.shared.global [%0], [%1], 16;\n"
                         :: "r"(sx + q * 16), "l"(gx + q * 4));
        const float* gw = &W[(size_t)(n0 + wrow) * ldw + k0 + wcol];
        unsigned sw = (unsigned)__cvta_generic_to_shared(&ws[wrow * GP + wcol]);
#pragma unroll
        for (int q = 0; q < WG; q++)
            asm volatile("cp.async.cg.shared.global [%0], [%1], 16;\n"
                         :: "r"(sw + q * 16), "l"(gw + q * 4));
        asm volatile("cp.async.commit_group;\n");
    };

#pragma unroll
    for (int i = 0; i < NSTG - 1; i++) prefetch(i);

#pragma unroll
    for (int s = 0; s < NS; s++) {
        if constexpr (NSTG == 2) {
            asm volatile("cp.async.wait_group 0;\n");
        } else {  // NSTG == 3
            if (s < NS - 1) asm volatile("cp.async.wait_group 1;\n");
            else            asm volatile("cp.async.wait_group 0;\n");
        }
        __syncthreads();
        if (s + NSTG - 1 < NS) prefetch(s + NSTG - 1);

        const float* xs = smem + (s % NSTG) * STAGE;
        const float* ws = xs + XTILE_F;

#pragma unroll
        for (int ks = 0; ks < 4; ks++) {
            const int kk = ks * 8;
            unsigned a[MT][4], b[NT][2];
#pragma unroll
            for (int mt = 0; mt < MT; mt++) {
                int rb = warp_m * (BM / 2) + mt * 16;
                a[mt][0] = __float_as_uint(xs[(rb + g    ) * GP + kk + tg    ]);
                a[mt][1] = __float_as_uint(xs[(rb + g + 8) * GP + kk + tg    ]);
                a[mt][2] = __float_as_uint(xs[(rb + g    ) * GP + kk + tg + 4]);
                a[mt][3] = __float_as_uint(xs[(rb + g + 8) * GP + kk + tg + 4]);
            }
#pragma unroll
            for (int nt = 0; nt < NT; nt++) {
                int nb = warp_n * (BN / 4) + nt * 8 + g;
                b[nt][0] = __float_as_uint(ws[nb * GP + kk + tg    ]);
                b[nt][1] = __float_as_uint(ws[nb * GP + kk + tg + 4]);
            }
#pragma unroll
            for (int mt = 0; mt < MT; mt++)
#pragma unroll
                for (int nt = 0; nt < NT; nt++)
                    MMA_TF32(c[mt][nt], a[mt][0], a[mt][1], a[mt][2], a[mt][3],
                             b[nt][0], b[nt][1]);
        }
    }

#pragma unroll
    for (int mt = 0; mt < MT; mt++) {
#pragma unroll
        for (int nt = 0; nt < NT; nt++) {
            int col = n0 + warp_n * (BN / 4) + nt * 8 + 2 * tg;
            float b0 = bias[col], b1 = bias[col + 1];
            int r0 = m0 + warp_m * (BM / 2) + mt * 16 + g;
            float v0 = c[mt][nt][0] + b0;
            float v1 = c[mt][nt][1] + b1;
            float v2 = c[mt][nt][2] + b0;
            float v3 = c[mt][nt][3] + b1;
            if (relu) {
                v0 = fmaxf(v0, 0.f); v1 = fmaxf(v1, 0.f);
                v2 = fmaxf(v2, 0.f); v3 = fmaxf(v3, 0.f);
            }
            Y[(size_t)r0 * N + col]           = v0;
            Y[(size_t)r0 * N + col + 1]       = v1;
            Y[(size_t)(r0 + 8) * N + col]     = v2;
            Y[(size_t)(r0 + 8) * N + col + 1] = v3;
        }
    }
}

#define SMEMB(BM,BN,NSTG) ((NSTG) * ((BM) + (BN)) * GP * 4)

// ---------------- residual + LayerNorm (row = 256) --------------------------
__global__ void add_ln_kernel(const float* __restrict__ A, const float* __restrict__ Bv,
                              const float* __restrict__ g, const float* __restrict__ be,
                              const float* __restrict__ qpos,
                              float* __restrict__ Y, float* __restrict__ Yq)
{
    int row = blockIdx.x, t = threadIdx.x;
    float x = A[(size_t)row * Cc + t] + Bv[(size_t)row * Cc + t];
    float s = x, s2 = x * x;
#pragma unroll
    for (int o = 16; o > 0; o >>= 1) {
        s  += __shfl_xor_sync(0xffffffffu, s, o);
        s2 += __shfl_xor_sync(0xffffffffu, s2, o);
    }
    __shared__ float ss[8], ss2[8];
    int w = t >> 5;
    if ((t & 31) == 0) { ss[w] = s; ss2[w] = s2; }
    __syncthreads();
    s = 0.f; s2 = 0.f;
#pragma unroll
    for (int i = 0; i < 8; i++) { s += ss[i]; s2 += ss2[i]; }
    float mean = s * (1.f / Cc);
    float var  = s2 * (1.f / Cc) - mean * mean;
    float inv  = rsqrtf(var + 1e-5f);
    float y = (x - mean) * inv * g[t] + be[t];
    Y[(size_t)row * Cc + t] = y;
    if (qpos) Yq[(size_t)row * Cc + t] = y + qpos[(size_t)row * Cc + t];
}

// residual + 4 split-K partials + LayerNorm
__global__ void add_ln4_kernel(const float* __restrict__ A, const float* __restrict__ P,
                               const float* __restrict__ g, const float* __restrict__ be,
                               float* __restrict__ Y)
{
    int row = blockIdx.x, t = threadIdx.x;
    size_t idx = (size_t)row * Cc + t;
    float x = A[idx] + P[idx] + P[idx + (size_t)MROWS*Cc]
            + P[idx + (size_t)2*MROWS*Cc] + P[idx + (size_t)3*MROWS*Cc];
    float s = x, s2 = x * x;
#pragma unroll
    for (int o = 16; o > 0; o >>= 1) {
        s  += __shfl_xor_sync(0xffffffffu, s, o);
        s2 += __shfl_xor_sync(0xffffffffu, s2, o);
    }
    __shared__ float ss[8], ss2[8];
    int w = t >> 5;
    if ((t & 31) == 0) { ss[w] = s; ss2[w] = s2; }
    __syncthreads();
    s = 0.f; s2 = 0.f;
#pragma unroll
    for (int i = 0; i < 8; i++) { s += ss[i]; s2 += ss2[i]; }
    float mean = s * (1.f / Cc);
    float var  = s2 * (1.f / Cc) - mean * mean;
    float inv  = rsqrtf(var + 1e-5f);
    Y[idx] = (x - mean) * inv * g[t] + be[t];
}

// ---------------- tensor-core flash attention, pipelined K/V staging --------
// grid (LQ/128, B*H), 256 thr. K chunks double-buffered via cp.async; V chunks
// staged through registers (LDG for c+1 issued after barrier, STS'd next iter).
#define KP 36
#define VP 68
#define ATTN_SMEMF (128*KP + 2*64*KP + 2*32*VP)
#define ATTN_SMEMB (ATTN_SMEMF*4)
__global__ __launch_bounds__(256, 2)
void attn_kernel(const float* __restrict__ Q, const float* __restrict__ K,
                 const float* __restrict__ V, float* __restrict__ O)
{
    extern __shared__ float sm[];
    float* Qs  = sm;
    float* Ks0 = sm + 128 * KP;
    float* Ks1 = Ks0 + 64 * KP;
    float* Vt0 = Ks1 + 64 * KP;
    float* Vt1 = Vt0 + 32 * VP;

    const int t = threadIdx.x;
    const int warp = t >> 5, lane = t & 31;
    const int g = lane >> 2, tg = lane & 3;
    const int bh = blockIdx.y;
    const int b = bh >> 3, h = bh & 7;
    const int q0 = blockIdx.x * 128;
    const size_t base = ((size_t)b * LQ) * Cc + h * DH;

    const int key = t & 63, dg = t >> 6;

    auto prefetchK = [&](int c0, float* Ks) {
#pragma unroll
        for (int j = 0; j < 2; j++) {
            int gl = t * 2 + j;
            int row = gl >> 3, seg = (gl & 7) * 4;
            const float* src = &K[base + (size_t)(c0 + row) * Cc + seg];
            unsigned dst = (unsigned)__cvta_generic_to_shared(&Ks[row * KP + seg]);
            asm volatile("cp.async.cg.shared.global [%0], [%1], 16;\n"
                         :: "r"(dst), "l"(src));
        }
        asm volatile("cp.async.commit_group;\n");
    };

    // stage Q (scaled)
#pragma unroll
    for (int j = 0; j < 4; j++) {
        int idx = j * 256 + t;
        int row = idx >> 3, c4 = (idx & 7) * 4;
        float4 v4 = *(const float4*)&Q[base + (size_t)(q0 + row) * Cc + c4];
        v4.x *= 0.17677669529663687f; v4.y *= 0.17677669529663687f;
        v4.z *= 0.17677669529663687f; v4.w *= 0.17677669529663687f;
        *(float4*)&Qs[row * KP + c4] = v4;
    }

    // prologue: K chunk 0 via cp.async, V chunk 0 into registers
    prefetchK(0, Ks0);
    float4 vr0 = *(const float4*)&V[base + (size_t)key * Cc + dg * 8];
    float4 vr1 = *(const float4*)&V[base + (size_t)key * Cc + dg * 8 + 4];

    __syncthreads();   // Q staged

    unsigned qa[4][4];
    {
        int r = warp * 16 + g;
#pragma unroll
        for (int kt = 0; kt < 4; kt++) {
            qa[kt][0] = __float_as_uint(Qs[r * KP + kt * 8 + tg]);
            qa[kt][1] = __float_as_uint(Qs[(r + 8) * KP + kt * 8 + tg]);
            qa[kt][2] = __float_as_uint(Qs[r * KP + kt * 8 + tg + 4]);
            qa[kt][3] = __float_as_uint(Qs[(r + 8) * KP + kt * 8 + tg + 4]);
        }
    }

    float o[4][4];
#pragma unroll
    for (int nt = 0; nt < 4; nt++)
#pragma unroll
        for (int r = 0; r < 4; r++) o[nt][r] = 0.f;
    float m0 = -1e30f, m1 = -1e30f, l0 = 0.f, l1 = 0.f;

#pragma unroll 1
    for (int c = 0; c < 16; c++) {
        const int buf = c & 1;
        float* Vt = buf ? Vt1 : Vt0;
        const float* Ks = buf ? Ks1 : Ks0;

        // store V(c) transposed (rna->tf32) from registers
        Vt[(dg * 8 + 0) * VP + key] = __uint_as_float(rna_tf32(vr0.x));
        Vt[(dg * 8 + 1) * VP + key] = __uint_as_float(rna_tf32(vr0.y));
        Vt[(dg * 8 + 2) * VP + key] = __uint_as_float(rna_tf32(vr0.z));
        Vt[(dg * 8 + 3) * VP + key] = __uint_as_float(rna_tf32(vr0.w));
        Vt[(dg * 8 + 4) * VP + key] = __uint_as_float(rna_tf32(vr1.x));
        Vt[(dg * 8 + 5) * VP + key] = __uint_as_float(rna_tf32(vr1.y));
        Vt[(dg * 8 + 6) * VP + key] = __uint_as_float(rna_tf32(vr1.z));
        Vt[(dg * 8 + 7) * VP + key] = __uint_as_float(rna_tf32(vr1.w));

        asm volatile("cp.async.wait_group 0;\n");
        __syncthreads();   // Ks[buf] arrived, Vt[buf] stored

        if (c < 15) {      // issue next-chunk loads (consumed next iteration)
            int c0n = (c + 1) * 64;
            prefetchK(c0n, buf ? Ks0 : Ks1);
            vr0 = *(const float4*)&V[base + (size_t)(c0n + key) * Cc + dg * 8];
            vr1 = *(const float4*)&V[base + (size_t)(c0n + key) * Cc + dg * 8 + 4];
        }

        // S = Q @ K^T
        float c_[8][4];
#pragma unroll
        for (int nt = 0; nt < 8; nt++)
#pragma unroll
            for (int r = 0; r < 4; r++) c_[nt][r] = 0.f;
#pragma unroll
        for (int kt = 0; kt < 4; kt++) {
#pragma unroll
            for (int nt = 0; nt < 8; nt++) {
                unsigned b0 = __float_as_uint(Ks[(nt * 8 + g) * KP + kt * 8 + tg]);
                unsigned b1 = __float_as_uint(Ks[(nt * 8 + g) * KP + kt * 8 + tg + 4]);
                MMA_TF32(c_[nt], qa[kt][0], qa[kt][1], qa[kt][2], qa[kt][3], b0, b1);
            }
        }

        // online softmax
        float mx0 = -1e30f, mx1 = -1e30f;
#pragma unroll
        for (int nt = 0; nt < 8; nt++) {
            mx0 = fmaxf(mx0, fmaxf(c_[nt][0], c_[nt][1]));
            mx1 = fmaxf(mx1, fmaxf(c_[nt][2], c_[nt][3]));
        }
        mx0 = fmaxf(mx0, __shfl_xor_sync(0xffffffffu, mx0, 1));
        mx0 = fmaxf(mx0, __shfl_xor_sync(0xffffffffu, mx0, 2));
        mx1 = fmaxf(mx1, __shfl_xor_sync(0xffffffffu, mx1, 1));
        mx1 = fmaxf(mx1, __shfl_xor_sync(0xffffffffu, mx1, 2));
        float mn0 = fmaxf(m0, mx0), mn1 = fmaxf(m1, mx1);
        float cor0 = __expf(m0 - mn0), cor1 = __expf(m1 - mn1);
        l0 *= cor0; l1 *= cor1;
#pragma unroll
        for (int nt = 0; nt < 4; nt++) {
            o[nt][0] *= cor0; o[nt][1] *= cor0;
            o[nt][2] *= cor1; o[nt][3] *= cor1;
        }
#pragma unroll
        for (int nt = 0; nt < 8; nt++) {
            float p0 = __expf(c_[nt][0] - mn0);
            float p1 = __expf(c_[nt][1] - mn0);
            float p2 = __expf(c_[nt][2] - mn1);
            float p3 = __expf(c_[nt][3] - mn1);
            l0 += p0 + p1; l1 += p2 + p3;
            c_[nt][0] = __uint_as_float(rna_tf32(p0));
            c_[nt][1] = __uint_as_float(rna_tf32(p1));
            c_[nt][2] = __uint_as_float(rna_tf32(p2));
            c_[nt][3] = __uint_as_float(rna_tf32(p3));
        }
        m0 = mn0; m1 = mn1;

        // O += P @ V (redistribute P via shfl to A-layout)
        const int src0 = (lane & ~3) | (tg >> 1);
        const int src2 = src0 + 2;
        const bool odd = tg & 1;
#pragma unroll
        for (int kt = 0; kt < 8; kt++) {
            float e00 = __shfl_sync(0xffffffffu, c_[kt][0], src0);
            float e01 = __shfl_sync(0xffffffffu, c_[kt][1], src0);
            float e10 = __shfl_sync(0xffffffffu, c_[kt][2], src0);
            float e11 = __shfl_sync(0xffffffffu, c_[kt][3], src0);
            float e20 = __shfl_sync(0xffffffffu, c_[kt][0], src2);
            float e21 = __shfl_sync(0xffffffffu, c_[kt][1], src2);
            float e30 = __shfl_sync(0xffffffffu, c_[kt][2], src2);
            float e31 = __shfl_sync(0xffffffffu, c_[kt][3], src2);
            unsigned a0 = __float_as_uint(odd ? e01 : e00);
            unsigned a1 = __float_as_uint(odd ? e11 : e10);
            unsigned a2 = __float_as_uint(odd ? e21 : e20);
            unsigned a3 = __float_as_uint(odd ? e31 : e30);
#pragma unroll
            for (int nt = 0; nt < 4; nt++) {
                unsigned b0 = __float_as_uint(Vt[(nt * 8 + g) * VP + kt * 8 + tg]);
                unsigned b1 = __float_as_uint(Vt[(nt * 8 + g) * VP + kt * 8 + tg + 4]);
                MMA_TF32(o[nt], a0, a1, a2, a3, b0, b1);
            }
        }
    }

    l0 += __shfl_xor_sync(0xffffffffu, l0, 1);
    l0 += __shfl_xor_sync(0xffffffffu, l0, 2);
    l1 += __shfl_xor_sync(0xffffffffu, l1, 1);
    l1 += __shfl_xor_sync(0xffffffffu, l1, 2);
    float inv0 = 1.f / l0, inv1 = 1.f / l1;

    int r0 = q0 + warp * 16 + g;
#pragma unroll
    for (int nt = 0; nt < 4; nt++) {
        int col = nt * 8 + 2 * tg;
        float2 w0 = make_float2(o[nt][0] * inv0, o[nt][1] * inv0);
        float2 w1 = make_float2(o[nt][2] * inv1, o[nt][3] * inv1);
        *(float2*)&O[base + (size_t)r0 * Cc + col]       = w0;
        *(float2*)&O[base + (size_t)(r0 + 8) * Cc + col] = w1;
    }
}

// ---------------- deformable sampling (warp per (b,q,h), lane = channel) ----
__global__ void deform_kernel(const float* __restrict__ val, const float* __restrict__ offs,
                              const float* __restrict__ awl, const float* __restrict__ ref,
                              float* __restrict__ out)
{
    const int gid  = blockIdx.x * 4 + (threadIdx.x >> 5);
    const int lane = threadIdx.x & 31;
    const int h   = gid & 7;
    const int row = gid >> 3;
    const int b   = row >> 10;

    float a[16];
    float mx = -1e30f;
#pragma unroll
    for (int i = 0; i < 16; i++) {
        a[i] = awl[(size_t)row * 128 + h * 16 + i];
        mx = fmaxf(mx, a[i]);
    }
    float ssum = 0.f;
#pragma unroll
    for (int i = 0; i < 16; i++) { a[i] = __expf(a[i] - mx); ssum += a[i]; }
    float invs = 1.f / ssum;

    const int starts[4] = {0, 16384, 20480, 21504};
    float acc = 0.f;
#pragma unroll
    for (int lvl = 0; lvl < 4; lvl++) {
        const int Wl = 128 >> lvl;
        const int Hl = 128 >> lvl;
        const int start = starts[lvl];
        float rx = ref[((size_t)row * 4 + lvl) * 2 + 0];
        float ry = ref[((size_t)row * 4 + lvl) * 2 + 1];
#pragma unroll
        for (int p = 0; p < 4; p++) {
            size_t obase = (size_t)row * 256 + (((h * 4 + lvl) * 4 + p) * 2);
            float ox = offs[obase + 0];
            float oy = offs[obase + 1];
            float x = rx * (float)Wl + ox - 0.5f;
            float y = ry * (float)Hl + oy - 0.5f;
            float xf = floorf(x), yf = floorf(y);
            int x0 = (int)xf, y0 = (int)yf;
            float wx1 = x - xf, wx0 = 1.f - wx1;
            float wy1 = y - yf, wy0 = 1.f - wy1;
            float aw = a[lvl * 4 + p] * invs;

            float w00 = wx0 * wy0 * aw, w10 = wx1 * wy0 * aw;
            float w01 = wx0 * wy1 * aw, w11 = wx1 * wy1 * aw;
#pragma unroll
            for (int cidx = 0; cidx < 4; cidx++) {
                int ix = x0 + (cidx & 1);
                int iy = y0 + (cidx >> 1);
                float w = (cidx == 0) ? w00 : (cidx == 1) ? w10 : (cidx == 2) ? w01 : w11;
                if (ix >= 0 && ix < Wl && iy >= 0 && iy < Hl) {
                    size_t idx = (size_t)(b * LSRC + start + iy * Wl + ix) * Cc + h * DH + lane;
                    acc += w * val[idx];
                }
            }
        }
    }
    out[(size_t)row * Cc + h * DH + lane] = acc;
}

// ---------------- launcher ---------------------------------------------------
extern "C" void kernel_launch(void* const* d_in, const int* in_sizes, int n_in,
                              void* d_out, int out_size)
{
    const float* tgt   = (const float*)d_in[0];
    const float* qpos  = (const float*)d_in[1];
    const float* refp  = (const float*)d_in[2];
    const float* src   = (const float*)d_in[3];
    const float* in_w  = (const float*)d_in[4];
    const float* in_b  = (const float*)d_in[5];
    const float* sa_w  = (const float*)d_in[6];
    const float* sa_b  = (const float*)d_in[7];
    const float* off_w = (const float*)d_in[8];
    const float* off_b = (const float*)d_in[9];
    const float* aw_w  = (const float*)d_in[10];
    const float* aw_b  = (const float*)d_in[11];
    const float* val_w = (const float*)d_in[12];
    const float* val_b = (const float*)d_in[13];
    const float* co_w  = (const float*)d_in[14];
    const float* co_b  = (const float*)d_in[15];
    const float* ln1_g = (const float*)d_in[16];
    const float* ln1_b = (const float*)d_in[17];
    const float* ln2_g = (const float*)d_in[18];
    const float* ln2_b = (const float*)d_in[19];
    const float* ln3_g = (const float*)d_in[20];
    const float* ln3_b = (const float*)d_in[21];
    const float* f1_w  = (const float*)d_in[22];
    const float* f1_b  = (const float*)d_in[23];
    const float* f2_w  = (const float*)d_in[24];
    const float* f2_b  = (const float*)d_in[25];
    float* out = (float*)d_out;

    float *qk, *qk2, *qkv, *attn, *tmp, *t1, *t2, *off, *aw, *val, *ffn, *part, *zero;
    cudaGetSymbolAddress((void**)&qk,   g_qk);
    cudaGetSymbolAddress((void**)&qk2,  g_qk2);
    cudaGetSymbolAddress((void**)&qkv,  g_qkv);
    cudaGetSymbolAddress((void**)&attn, g_attn);
    cudaGetSymbolAddress((void**)&tmp,  g_tmp);
    cudaGetSymbolAddress((void**)&t1,   g_tgt1);
    cudaGetSymbolAddress((void**)&t2,   g_tgt2);
    cudaGetSymbolAddress((void**)&off,  g_off);
    cudaGetSymbolAddress((void**)&aw,   g_aw);
    cudaGetSymbolAddress((void**)&val,  g_val);
    cudaGetSymbolAddress((void**)&ffn,  g_ffn);
    cudaGetSymbolAddress((void**)&part, g_part);
    cudaGetSymbolAddress((void**)&zero, g_zero);

    static cudaStream_t s1;
    static cudaEvent_t evFork, evJoin;
    static int inited = 0;
    if (!inited) {
        cudaStreamCreateWithFlags(&s1, cudaStreamNonBlocking);
        cudaEventCreateWithFlags(&evFork, cudaEventDisableTiming);
        cudaEventCreateWithFlags(&evJoin, cudaEventDisableTiming);
        cudaFuncSetAttribute(gemm_tc<256,64,64,3>,
                             cudaFuncAttributeMaxDynamicSharedMemorySize, SMEMB(64,64,3));
        cudaFuncSetAttribute(gemm_tc<256,128,64,3>,
                             cudaFuncAttributeMaxDynamicSharedMemorySize, SMEMB(128,64,3));
        cudaFuncSetAttribute(gemm_tc<256,128,128,2>,
                             cudaFuncAttributeMaxDynamicSharedMemorySize, SMEMB(128,128,2));
        cudaFuncSetAttribute(attn_kernel,
                             cudaFuncAttributeMaxDynamicSharedMemorySize, ATTN_SMEMB);
        inited = 1;
    }

    const int NTOT = MROWS * Cc;

    // 1) qk = tgt + query_pos
    add_kernel<<<(NTOT + 255) / 256, 256>>>(tgt, qpos, qk, NTOT);

    // fork: value projection on side stream (depends only on src)
    cudaEventRecord(evFork, 0);
    cudaStreamWaitEvent(s1, evFork, 0);
    gemm_tc<256,128,128,2><<<dim3(2, VROWS / 128), 256, SMEMB(128,128,2), s1>>>(
        src, nullptr, val_w, val_b, val, VROWS, Cc, 0, 0,
        nullptr, nullptr, nullptr, 0, 256, 256);
    cudaEventRecord(evJoin, s1);

    // 2) Q/K/V projections — batched over grid.z
    gemm_tc<256,64,64,3><<<dim3(4, 64, 3), 256, SMEMB(64,64,3)>>>(
        qk, tgt, in_w, in_b, qkv, MROWS, Cc, 0, 1,
        nullptr, nullptr, nullptr, 0, 256, 256);

    // 3) attention (pipelined tensor-core flash, direct output)
    attn_kernel<<<dim3(LQ / 128, Bz * Hh), 256, ATTN_SMEMB>>>(
        qkv, qkv + MROWS * Cc, qkv + 2 * MROWS * Cc, attn);

    // 4) self-attn out proj + residual + LN(ln2) -> t1, and qk2 = t1 + qpos
    gemm_tc<256,64,64,3><<<dim3(4, 64), 256, SMEMB(64,64,3)>>>(
        attn, nullptr, sa_w, sa_b, tmp, MROWS, Cc, 0, 0,
        nullptr, nullptr, nullptr, 0, 256, 256);
    add_ln_kernel<<<MROWS, 256>>>(tgt, tmp, ln2_g, ln2_b, qpos, t1, qk2);

    // 5+6) offsets + attention weights in one z-batched launch
    gemm_tc<256,64,64,3><<<dim3(4, 64, 2), 256, SMEMB(64,64,3)>>>(
        qk2, nullptr, off_w, off_b, off, MROWS, Cc, 0, 2,
        aw_w, aw_b, aw, 128, 256, 256);

    // join value projection, then deformable sampling
    cudaStreamWaitEvent(0, evJoin, 0);
    deform_kernel<<<(MROWS * Hh) / 4, 128>>>(val, off, aw, refp, attn);

    // 8) co proj + residual + LN(ln1) -> t2
    gemm_tc<256,64,64,3><<<dim3(4, 64), 256, SMEMB(64,64,3)>>>(
        attn, nullptr, co_w, co_b, tmp, MROWS, Cc, 0, 0,
        nullptr, nullptr, nullptr, 0, 256, 256);
    add_ln_kernel<<<MROWS, 256>>>(t1, tmp, ln1_g, ln1_b, nullptr, t2, nullptr);

    // 9) FFN: f1 (relu), f2 split-K over z=4, fused reduce+LN
    gemm_tc<256,128,64,3><<<dim3(16, 32), 256, SMEMB(128,64,3)>>>(
        t2, nullptr, f1_w, f1_b, ffn, MROWS, DFF, 1, 0,
        nullptr, nullptr, nullptr, 0, 256, 256);
    gemm_tc<256,64,64,3><<<dim3(4, 64, 4), 256, SMEMB(64,64,3)>>>(
        ffn, nullptr, f2_w, f2_b, part, MROWS, Cc, 0, 3,
        nullptr, zero, nullptr, 0, 1024, 1024);
    add_ln4_kernel<<<MROWS, 256>>>(t2, part, ln3_g, ln3_b, out);
}

// round 14
// speedup vs baseline: 1.0819x; 1.0300x over previous
#include <cuda_runtime.h>
#include <cuda_bf16.h>
#include <math.h>

#define Bz   4
#define LQ   1024
#define Cc   256
#define Hh   8
#define DH   32
#define DFF  1024
#define LSRC 21760
#define MROWS (Bz*LQ)        // 4096
#define VROWS (Bz*LSRC)      // 87040

// ---------------- scratch (static device globals) ---------------------------
__device__ float g_qk  [MROWS*Cc];
__device__ float g_qk2 [MROWS*Cc];
__device__ float g_qkv [3*MROWS*Cc];
__device__ float g_attn[MROWS*Cc];
__device__ float g_tmp [MROWS*Cc];
__device__ float g_tgt1[MROWS*Cc];
__device__ float g_tgt2[MROWS*Cc];
__device__ float g_off [MROWS*Cc];
__device__ float g_aw  [MROWS*128];
__device__ float g_val [VROWS*Cc];
__device__ float g_ffn [MROWS*DFF];
__device__ float g_part[4*MROWS*Cc];
__device__ float g_zero[DFF];          // zero-initialized

__device__ __forceinline__ unsigned pack_bf16(float lo, float hi) {
    unsigned r;
    asm("cvt.rn.bf16x2.f32 %0, %1, %2;" : "=r"(r) : "f"(hi), "f"(lo));
    return r;
}

#define MMA_TF32(C, A0,A1,A2,A3, B0,B1) \
    asm volatile("mma.sync.aligned.m16n8k8.row.col.f32.tf32.tf32.f32 " \
                 "{%0,%1,%2,%3}, {%4,%5,%6,%7}, {%8,%9}, {%0,%1,%2,%3};" \
                 : "+f"(C[0]), "+f"(C[1]), "+f"(C[2]), "+f"(C[3]) \
                 : "r"(A0), "r"(A1), "r"(A2), "r"(A3), "r"(B0), "r"(B1))

#define MMA_BF16(C, A0,A1,A2,A3, B0,B1) \
    asm volatile("mma.sync.aligned.m16n8k16.row.col.f32.bf16.bf16.f32 " \
                 "{%0,%1,%2,%3}, {%4,%5,%6,%7}, {%8,%9}, {%0,%1,%2,%3};" \
                 : "+f"(C[0]), "+f"(C[1]), "+f"(C[2]), "+f"(C[3]) \
                 : "r"(A0), "r"(A1), "r"(A2), "r"(A3), "r"(B0), "r"(B1))

// ---------------- elementwise add ------------------------------------------
__global__ void add_kernel(const float* __restrict__ a, const float* __restrict__ b,
                           float* __restrict__ y, int n)
{
    int i = blockIdx.x * 256 + threadIdx.x;
    if (i < n) y[i] = a[i] + b[i];
}

// ---------------- tf32 tensor-core GEMM, NSTG-stage cp.async pipeline -------
#define GP 36
template<int K, int BM, int BN, int NSTG>
__global__ __launch_bounds__(256, 2)
void gemm_tc(const float* __restrict__ X, const float* __restrict__ Xalt,
             const float* __restrict__ W, const float* __restrict__ bias,
             float* __restrict__ Y, int M, int N, int relu, int mode,
             const float* __restrict__ W2, const float* __restrict__ b2,
             float* __restrict__ Y2, int N2, int ldx, int ldw)
{
    extern __shared__ float smem[];
    constexpr int MT = BM / 32;
    constexpr int NT = BN / 32;
    constexpr int XTILE_F = BM * GP;
    constexpr int STAGE = (BM + BN) * GP;
    constexpr int NS = K >> 5;
    constexpr int TPRX = 256 / BM;
    constexpr int XG   = (32 / TPRX) / 4;
    constexpr int TPRW = 256 / BN;
    constexpr int WG   = (32 / TPRW) / 4;

    const int z = blockIdx.z;
    if (mode == 1 && z) {
        W    += (size_t)z * 256 * K;
        bias += z * 256;
        Y    += (size_t)z * M * N;
        if (z == 2) X = Xalt;
    } else if (mode == 2 && z) {
        if (blockIdx.x >= 2) return;
        W = W2; bias = b2; Y = Y2; N = N2;
    } else if (mode == 3) {
        X += z * K;
        W += z * K;
        Y += (size_t)z * M * N;
        if (z) bias = b2;
    }

    const int t    = threadIdx.x;
    const int warp = t >> 5;
    const int lane = t & 31;
    const int g    = lane >> 2;
    const int tg   = lane & 3;
    const int warp_m = warp >> 2;
    const int warp_n = warp & 3;
    const int m0 = blockIdx.y * BM;
    const int n0 = blockIdx.x * BN;

    const int xrow = t / TPRX;
    const int xcol = (t % TPRX) * (32 / TPRX);
    const int wrow = t / TPRW;
    const int wcol = (t % TPRW) * (32 / TPRW);

    float c[MT][NT][4];
#pragma unroll
    for (int i = 0; i < MT; i++)
#pragma unroll
        for (int j = 0; j < NT; j++)
#pragma unroll
            for (int r = 0; r < 4; r++) c[i][j][r] = 0.f;

    auto prefetch = [&](int s) {
        const int k0 = s << 5;
        float* xs = smem + (s % NSTG) * STAGE;
        float* ws = xs + XTILE_F;
        const float* gx = &X[(size_t)(m0 + xrow) * ldx + k0 + xcol];
        unsigned sx = (unsigned)__cvta_generic_to_shared(&xs[xrow * GP + xcol]);
#pragma unroll
        for (int q = 0; q < XG; q++)
            asm volatile("cp.async.cg.shared.global [%0], [%1], 16;\n"
                         :: "r"(sx + q * 16), "l"(gx + q * 4));
        const float* gw = &W[(size_t)(n0 + wrow) * ldw + k0 + wcol];
        unsigned sw = (unsigned)__cvta_generic_to_shared(&ws[wrow * GP + wcol]);
#pragma unroll
        for (int q = 0; q < WG; q++)
            asm volatile("cp.async.cg.shared.global [%0], [%1], 16;\n"
                         :: "r"(sw + q * 16), "l"(gw + q * 4));
        asm volatile("cp.async.commit_group;\n");
    };

#pragma unroll
    for (int i = 0; i < NSTG - 1; i++) prefetch(i);

#pragma unroll
    for (int s = 0; s < NS; s++) {
        if constexpr (NSTG == 2) {
            asm volatile("cp.async.wait_group 0;\n");
        } else {  // NSTG == 3
            if (s < NS - 1) asm volatile("cp.async.wait_group 1;\n");
            else            asm volatile("cp.async.wait_group 0;\n");
        }
        __syncthreads();
        if (s + NSTG - 1 < NS) prefetch(s + NSTG - 1);

        const float* xs = smem + (s % NSTG) * STAGE;
        const float* ws = xs + XTILE_F;

#pragma unroll
        for (int ks = 0; ks < 4; ks++) {
            const int kk = ks * 8;
            unsigned a[MT][4], b[NT][2];
#pragma unroll
            for (int mt = 0; mt < MT; mt++) {
                int rb = warp_m * (BM / 2) + mt * 16;
                a[mt][0] = __float_as_uint(xs[(rb + g    ) * GP + kk + tg    ]);
                a[mt][1] = __float_as_uint(xs[(rb + g + 8) * GP + kk + tg    ]);
                a[mt][2] = __float_as_uint(xs[(rb + g    ) * GP + kk + tg + 4]);
                a[mt][3] = __float_as_uint(xs[(rb + g + 8) * GP + kk + tg + 4]);
            }
#pragma unroll
            for (int nt = 0; nt < NT; nt++) {
                int nb = warp_n * (BN / 4) + nt * 8 + g;
                b[nt][0] = __float_as_uint(ws[nb * GP + kk + tg    ]);
                b[nt][1] = __float_as_uint(ws[nb * GP + kk + tg + 4]);
            }
#pragma unroll
            for (int mt = 0; mt < MT; mt++)
#pragma unroll
                for (int nt = 0; nt < NT; nt++)
                    MMA_TF32(c[mt][nt], a[mt][0], a[mt][1], a[mt][2], a[mt][3],
                             b[nt][0], b[nt][1]);
        }
    }

#pragma unroll
    for (int mt = 0; mt < MT; mt++) {
#pragma unroll
        for (int nt = 0; nt < NT; nt++) {
            int col = n0 + warp_n * (BN / 4) + nt * 8 + 2 * tg;
            float b0 = bias[col], b1 = bias[col + 1];
            int r0 = m0 + warp_m * (BM / 2) + mt * 16 + g;
            float v0 = c[mt][nt][0] + b0;
            float v1 = c[mt][nt][1] + b1;
            float v2 = c[mt][nt][2] + b0;
            float v3 = c[mt][nt][3] + b1;
            if (relu) {
                v0 = fmaxf(v0, 0.f); v1 = fmaxf(v1, 0.f);
                v2 = fmaxf(v2, 0.f); v3 = fmaxf(v3, 0.f);
            }
            Y[(size_t)r0 * N + col]           = v0;
            Y[(size_t)r0 * N + col + 1]       = v1;
            Y[(size_t)(r0 + 8) * N + col]     = v2;
            Y[(size_t)(r0 + 8) * N + col + 1] = v3;
        }
    }
}

#define SMEMB(BM,BN,NSTG) ((NSTG) * ((BM) + (BN)) * GP * 4)

// ---------------- residual + LayerNorm (row = 256) --------------------------
__global__ void add_ln_kernel(const float* __restrict__ A, const float* __restrict__ Bv,
                              const float* __restrict__ g, const float* __restrict__ be,
                              const float* __restrict__ qpos,
                              float* __restrict__ Y, float* __restrict__ Yq)
{
    int row = blockIdx.x, t = threadIdx.x;
    float x = A[(size_t)row * Cc + t] + Bv[(size_t)row * Cc + t];
    float s = x, s2 = x * x;
#pragma unroll
    for (int o = 16; o > 0; o >>= 1) {
        s  += __shfl_xor_sync(0xffffffffu, s, o);
        s2 += __shfl_xor_sync(0xffffffffu, s2, o);
    }
    __shared__ float ss[8], ss2[8];
    int w = t >> 5;
    if ((t & 31) == 0) { ss[w] = s; ss2[w] = s2; }
    __syncthreads();
    s = 0.f; s2 = 0.f;
#pragma unroll
    for (int i = 0; i < 8; i++) { s += ss[i]; s2 += ss2[i]; }
    float mean = s * (1.f / Cc);
    float var  = s2 * (1.f / Cc) - mean * mean;
    float inv  = rsqrtf(var + 1e-5f);
    float y = (x - mean) * inv * g[t] + be[t];
    Y[(size_t)row * Cc + t] = y;
    if (qpos) Yq[(size_t)row * Cc + t] = y + qpos[(size_t)row * Cc + t];
}

// residual + 4 split-K partials + LayerNorm
__global__ void add_ln4_kernel(const float* __restrict__ A, const float* __restrict__ P,
                               const float* __restrict__ g, const float* __restrict__ be,
                               float* __restrict__ Y)
{
    int row = blockIdx.x, t = threadIdx.x;
    size_t idx = (size_t)row * Cc + t;
    float x = A[idx] + P[idx] + P[idx + (size_t)MROWS*Cc]
            + P[idx + (size_t)2*MROWS*Cc] + P[idx + (size_t)3*MROWS*Cc];
    float s = x, s2 = x * x;
#pragma unroll
    for (int o = 16; o > 0; o >>= 1) {
        s  += __shfl_xor_sync(0xffffffffu, s, o);
        s2 += __shfl_xor_sync(0xffffffffu, s2, o);
    }
    __shared__ float ss[8], ss2[8];
    int w = t >> 5;
    if ((t & 31) == 0) { ss[w] = s; ss2[w] = s2; }
    __syncthreads();
    s = 0.f; s2 = 0.f;
#pragma unroll
    for (int i = 0; i < 8; i++) { s += ss[i]; s2 += ss2[i]; }
    float mean = s * (1.f / Cc);
    float var  = s2 * (1.f / Cc) - mean * mean;
    float inv  = rsqrtf(var + 1e-5f);
    Y[idx] = (x - mean) * inv * g[t] + be[t];
}

// ---------------- tensor-core flash attention -------------------------------
// QK^T in tf32, PV in bf16 m16n8k16 (S C-fragment packs directly into PV
// A-fragment -> zero shuffles). K double-buffered cp.async; V staged through
// registers and stored as bf16x2 Vt32[ch][keypair] (pitch 36 words, bank =
// 4g+tg -> conflict-free fragment loads).
#define KP 36
#define ATTN_SMEMF (128*KP + 2*64*KP + 2*32*36)
#define ATTN_SMEMB (ATTN_SMEMF*4)
__global__ __launch_bounds__(256, 2)
void attn_kernel(const float* __restrict__ Q, const float* __restrict__ K,
                 const float* __restrict__ V, float* __restrict__ O)
{
    extern __shared__ float sm[];
    float* Qs  = sm;
    float* Ks0 = sm + 128 * KP;
    float* Ks1 = Ks0 + 64 * KP;
    unsigned* Vt0 = (unsigned*)(Ks1 + 64 * KP);
    unsigned* Vt1 = Vt0 + 32 * 36;

    const int t = threadIdx.x;
    const int warp = t >> 5, lane = t & 31;
    const int g = lane >> 2, tg = lane & 3;
    const int bh = blockIdx.y;
    const int b = bh >> 3, h = bh & 7;
    const int q0 = blockIdx.x * 128;
    const size_t base = ((size_t)b * LQ) * Cc + h * DH;

    const int kp  = lane;        // keypair 0..31 (keys 2kp, 2kp+1)
    const int ch0 = warp * 4;    // 4 channels per warp

    auto prefetchK = [&](int c0, float* Ks) {
#pragma unroll
        for (int j = 0; j < 2; j++) {
            int gl = t * 2 + j;
            int row = gl >> 3, seg = (gl & 7) * 4;
            const float* src = &K[base + (size_t)(c0 + row) * Cc + seg];
            unsigned dst = (unsigned)__cvta_generic_to_shared(&Ks[row * KP + seg]);
            asm volatile("cp.async.cg.shared.global [%0], [%1], 16;\n"
                         :: "r"(dst), "l"(src));
        }
        asm volatile("cp.async.commit_group;\n");
    };

    // stage Q (scaled)
#pragma unroll
    for (int j = 0; j < 4; j++) {
        int idx = j * 256 + t;
        int row = idx >> 3, c4 = (idx & 7) * 4;
        float4 v4 = *(const float4*)&Q[base + (size_t)(q0 + row) * Cc + c4];
        v4.x *= 0.17677669529663687f; v4.y *= 0.17677669529663687f;
        v4.z *= 0.17677669529663687f; v4.w *= 0.17677669529663687f;
        *(float4*)&Qs[row * KP + c4] = v4;
    }

    // prologue: K chunk 0 via cp.async, V chunk 0 into registers
    prefetchK(0, Ks0);
    float4 vk0 = *(const float4*)&V[base + (size_t)(2 * kp)     * Cc + ch0];
    float4 vk1 = *(const float4*)&V[base + (size_t)(2 * kp + 1) * Cc + ch0];

    __syncthreads();   // Q staged

    unsigned qa[4][4];
    {
        int r = warp * 16 + g;
#pragma unroll
        for (int kt = 0; kt < 4; kt++) {
            qa[kt][0] = __float_as_uint(Qs[r * KP + kt * 8 + tg]);
            qa[kt][1] = __float_as_uint(Qs[(r + 8) * KP + kt * 8 + tg]);
            qa[kt][2] = __float_as_uint(Qs[r * KP + kt * 8 + tg + 4]);
            qa[kt][3] = __float_as_uint(Qs[(r + 8) * KP + kt * 8 + tg + 4]);
        }
    }

    float o[4][4];
#pragma unroll
    for (int nt = 0; nt < 4; nt++)
#pragma unroll
        for (int r = 0; r < 4; r++) o[nt][r] = 0.f;
    float m0 = -1e30f, m1 = -1e30f, l0 = 0.f, l1 = 0.f;

#pragma unroll 1
    for (int c = 0; c < 16; c++) {
        const int buf = c & 1;
        unsigned* Vt = buf ? Vt1 : Vt0;
        const float* Ks = buf ? Ks1 : Ks0;

        // store V(c) as bf16x2 (lo = even key)
        Vt[(ch0 + 0) * 36 + kp] = pack_bf16(vk0.x, vk1.x);
        Vt[(ch0 + 1) * 36 + kp] = pack_bf16(vk0.y, vk1.y);
        Vt[(ch0 + 2) * 36 + kp] = pack_bf16(vk0.z, vk1.z);
        Vt[(ch0 + 3) * 36 + kp] = pack_bf16(vk0.w, vk1.w);

        asm volatile("cp.async.wait_group 0;\n");
        __syncthreads();   // Ks[buf] arrived, Vt[buf] stored

        if (c < 15) {      // issue next-chunk loads (consumed next iteration)
            int c0n = (c + 1) * 64;
            prefetchK(c0n, buf ? Ks0 : Ks1);
            vk0 = *(const float4*)&V[base + (size_t)(c0n + 2 * kp)     * Cc + ch0];
            vk1 = *(const float4*)&V[base + (size_t)(c0n + 2 * kp + 1) * Cc + ch0];
        }

        // S = Q @ K^T (tf32)
        float c_[8][4];
#pragma unroll
        for (int nt = 0; nt < 8; nt++)
#pragma unroll
            for (int r = 0; r < 4; r++) c_[nt][r] = 0.f;
#pragma unroll
        for (int kt = 0; kt < 4; kt++) {
#pragma unroll
            for (int nt = 0; nt < 8; nt++) {
                unsigned b0 = __float_as_uint(Ks[(nt * 8 + g) * KP + kt * 8 + tg]);
                unsigned b1 = __float_as_uint(Ks[(nt * 8 + g) * KP + kt * 8 + tg + 4]);
                MMA_TF32(c_[nt], qa[kt][0], qa[kt][1], qa[kt][2], qa[kt][3], b0, b1);
            }
        }

        // online softmax (rows g, g+8; quad reductions)
        float mx0 = -1e30f, mx1 = -1e30f;
#pragma unroll
        for (int nt = 0; nt < 8; nt++) {
            mx0 = fmaxf(mx0, fmaxf(c_[nt][0], c_[nt][1]));
            mx1 = fmaxf(mx1, fmaxf(c_[nt][2], c_[nt][3]));
        }
        mx0 = fmaxf(mx0, __shfl_xor_sync(0xffffffffu, mx0, 1));
        mx0 = fmaxf(mx0, __shfl_xor_sync(0xffffffffu, mx0, 2));
        mx1 = fmaxf(mx1, __shfl_xor_sync(0xffffffffu, mx1, 1));
        mx1 = fmaxf(mx1, __shfl_xor_sync(0xffffffffu, mx1, 2));
        float mn0 = fmaxf(m0, mx0), mn1 = fmaxf(m1, mx1);
        float cor0 = __expf(m0 - mn0), cor1 = __expf(m1 - mn1);
        l0 *= cor0; l1 *= cor1;
#pragma unroll
        for (int nt = 0; nt < 4; nt++) {
            o[nt][0] *= cor0; o[nt][1] *= cor0;
            o[nt][2] *= cor1; o[nt][3] *= cor1;
        }
#pragma unroll
        for (int nt = 0; nt < 8; nt++) {
            c_[nt][0] = __expf(c_[nt][0] - mn0);
            c_[nt][1] = __expf(c_[nt][1] - mn0);
            c_[nt][2] = __expf(c_[nt][2] - mn1);
            c_[nt][3] = __expf(c_[nt][3] - mn1);
            l0 += c_[nt][0] + c_[nt][1];
            l1 += c_[nt][2] + c_[nt][3];
        }
        m0 = mn0; m1 = mn1;

        // O += P @ V (bf16 m16n8k16; S C-fragment == PV A-fragment layout)
#pragma unroll
        for (int kt = 0; kt < 4; kt++) {
            unsigned a0 = pack_bf16(c_[2*kt  ][0], c_[2*kt  ][1]);
            unsigned a1 = pack_bf16(c_[2*kt  ][2], c_[2*kt  ][3]);
            unsigned a2 = pack_bf16(c_[2*kt+1][0], c_[2*kt+1][1]);
            unsigned a3 = pack_bf16(c_[2*kt+1][2], c_[2*kt+1][3]);
#pragma unroll
            for (int nt = 0; nt < 4; nt++) {
                unsigned b0 = Vt[(8*nt + g) * 36 + 8*kt + tg];
                unsigned b1 = Vt[(8*nt + g) * 36 + 8*kt + tg + 4];
                MMA_BF16(o[nt], a0, a1, a2, a3, b0, b1);
            }
        }
    }

    l0 += __shfl_xor_sync(0xffffffffu, l0, 1);
    l0 += __shfl_xor_sync(0xffffffffu, l0, 2);
    l1 += __shfl_xor_sync(0xffffffffu, l1, 1);
    l1 += __shfl_xor_sync(0xffffffffu, l1, 2);
    float inv0 = 1.f / l0, inv1 = 1.f / l1;

    int r0 = q0 + warp * 16 + g;
#pragma unroll
    for (int nt = 0; nt < 4; nt++) {
        int col = nt * 8 + 2 * tg;
        float2 w0 = make_float2(o[nt][0] * inv0, o[nt][1] * inv0);
        float2 w1 = make_float2(o[nt][2] * inv1, o[nt][3] * inv1);
        *(float2*)&O[base + (size_t)r0 * Cc + col]       = w0;
        *(float2*)&O[base + (size_t)(r0 + 8) * Cc + col] = w1;
    }
}

// ---------------- deformable sampling (warp per (b,q,h), lane = channel) ----
__global__ void deform_kernel(const float* __restrict__ val, const float* __restrict__ offs,
                              const float* __restrict__ awl, const float* __restrict__ ref,
                              float* __restrict__ out)
{
    const int gid  = blockIdx.x * 4 + (threadIdx.x >> 5);
    const int lane = threadIdx.x & 31;
    const int h   = gid & 7;
    const int row = gid >> 3;
    const int b   = row >> 10;

    float a[16];
    float mx = -1e30f;
#pragma unroll
    for (int i = 0; i < 16; i++) {
        a[i] = awl[(size_t)row * 128 + h * 16 + i];
        mx = fmaxf(mx, a[i]);
    }
    float ssum = 0.f;
#pragma unroll
    for (int i = 0; i < 16; i++) { a[i] = __expf(a[i] - mx); ssum += a[i]; }
    float invs = 1.f / ssum;

    const int starts[4] = {0, 16384, 20480, 21504};
    float acc = 0.f;
#pragma unroll
    for (int lvl = 0; lvl < 4; lvl++) {
        const int Wl = 128 >> lvl;
        const int Hl = 128 >> lvl;
        const int start = starts[lvl];
        float rx = ref[((size_t)row * 4 + lvl) * 2 + 0];
        float ry = ref[((size_t)row * 4 + lvl) * 2 + 1];
#pragma unroll
        for (int p = 0; p < 4; p++) {
            size_t obase = (size_t)row * 256 + (((h * 4 + lvl) * 4 + p) * 2);
            float ox = offs[obase + 0];
            float oy = offs[obase + 1];
            float x = rx * (float)Wl + ox - 0.5f;
            float y = ry * (float)Hl + oy - 0.5f;
            float xf = floorf(x), yf = floorf(y);
            int x0 = (int)xf, y0 = (int)yf;
            float wx1 = x - xf, wx0 = 1.f - wx1;
            float wy1 = y - yf, wy0 = 1.f - wy1;
            float aw = a[lvl * 4 + p] * invs;

            float w00 = wx0 * wy0 * aw, w10 = wx1 * wy0 * aw;
            float w01 = wx0 * wy1 * aw, w11 = wx1 * wy1 * aw;
#pragma unroll
            for (int cidx = 0; cidx < 4; cidx++) {
                int ix = x0 + (cidx & 1);
                int iy = y0 + (cidx >> 1);
                float w = (cidx == 0) ? w00 : (cidx == 1) ? w10 : (cidx == 2) ? w01 : w11;
                if (ix >= 0 && ix < Wl && iy >= 0 && iy < Hl) {
                    size_t idx = (size_t)(b * LSRC + start + iy * Wl + ix) * Cc + h * DH + lane;
                    acc += w * val[idx];
                }
            }
        }
    }
    out[(size_t)row * Cc + h * DH + lane] = acc;
}

// ---------------- launcher ---------------------------------------------------
extern "C" void kernel_launch(void* const* d_in, const int* in_sizes, int n_in,
                              void* d_out, int out_size)
{
    const float* tgt   = (const float*)d_in[0];
    const float* qpos  = (const float*)d_in[1];
    const float* refp  = (const float*)d_in[2];
    const float* src   = (const float*)d_in[3];
    const float* in_w  = (const float*)d_in[4];
    const float* in_b  = (const float*)d_in[5];
    const float* sa_w  = (const float*)d_in[6];
    const float* sa_b  = (const float*)d_in[7];
    const float* off_w = (const float*)d_in[8];
    const float* off_b = (const float*)d_in[9];
    const float* aw_w  = (const float*)d_in[10];
    const float* aw_b  = (const float*)d_in[11];
    const float* val_w = (const float*)d_in[12];
    const float* val_b = (const float*)d_in[13];
    const float* co_w  = (const float*)d_in[14];
    const float* co_b  = (const float*)d_in[15];
    const float* ln1_g = (const float*)d_in[16];
    const float* ln1_b = (const float*)d_in[17];
    const float* ln2_g = (const float*)d_in[18];
    const float* ln2_b = (const float*)d_in[19];
    const float* ln3_g = (const float*)d_in[20];
    const float* ln3_b = (const float*)d_in[21];
    const float* f1_w  = (const float*)d_in[22];
    const float* f1_b  = (const float*)d_in[23];
    const float* f2_w  = (const float*)d_in[24];
    const float* f2_b  = (const float*)d_in[25];
    float* out = (float*)d_out;

    float *qk, *qk2, *qkv, *attn, *tmp, *t1, *t2, *off, *aw, *val, *ffn, *part, *zero;
    cudaGetSymbolAddress((void**)&qk,   g_qk);
    cudaGetSymbolAddress((void**)&qk2,  g_qk2);
    cudaGetSymbolAddress((void**)&qkv,  g_qkv);
    cudaGetSymbolAddress((void**)&attn, g_attn);
    cudaGetSymbolAddress((void**)&tmp,  g_tmp);
    cudaGetSymbolAddress((void**)&t1,   g_tgt1);
    cudaGetSymbolAddress((void**)&t2,   g_tgt2);
    cudaGetSymbolAddress((void**)&off,  g_off);
    cudaGetSymbolAddress((void**)&aw,   g_aw);
    cudaGetSymbolAddress((void**)&val,  g_val);
    cudaGetSymbolAddress((void**)&ffn,  g_ffn);
    cudaGetSymbolAddress((void**)&part, g_part);
    cudaGetSymbolAddress((void**)&zero, g_zero);

    static cudaStream_t s1;
    static cudaEvent_t evFork, evJoin;
    static int inited = 0;
    if (!inited) {
        cudaStreamCreateWithFlags(&s1, cudaStreamNonBlocking);
        cudaEventCreateWithFlags(&evFork, cudaEventDisableTiming);
        cudaEventCreateWithFlags(&evJoin, cudaEventDisableTiming);
        cudaFuncSetAttribute(gemm_tc<256,64,64,3>,
                             cudaFuncAttributeMaxDynamicSharedMemorySize, SMEMB(64,64,3));
        cudaFuncSetAttribute(gemm_tc<256,128,64,3>,
                             cudaFuncAttributeMaxDynamicSharedMemorySize, SMEMB(128,64,3));
        cudaFuncSetAttribute(gemm_tc<256,128,128,2>,
                             cudaFuncAttributeMaxDynamicSharedMemorySize, SMEMB(128,128,2));
        cudaFuncSetAttribute(attn_kernel,
                             cudaFuncAttributeMaxDynamicSharedMemorySize, ATTN_SMEMB);
        inited = 1;
    }

    const int NTOT = MROWS * Cc;

    // 1) qk = tgt + query_pos
    add_kernel<<<(NTOT + 255) / 256, 256>>>(tgt, qpos, qk, NTOT);

    // fork: value projection on side stream (depends only on src)
    cudaEventRecord(evFork, 0);
    cudaStreamWaitEvent(s1, evFork, 0);
    gemm_tc<256,128,128,2><<<dim3(2, VROWS / 128), 256, SMEMB(128,128,2), s1>>>(
        src, nullptr, val_w, val_b, val, VROWS, Cc, 0, 0,
        nullptr, nullptr, nullptr, 0, 256, 256);
    cudaEventRecord(evJoin, s1);

    // 2) Q/K/V projections — batched over grid.z
    gemm_tc<256,64,64,3><<<dim3(4, 64, 3), 256, SMEMB(64,64,3)>>>(
        qk, tgt, in_w, in_b, qkv, MROWS, Cc, 0, 1,
        nullptr, nullptr, nullptr, 0, 256, 256);

    // 3) attention (pipelined tensor-core flash, bf16 PV)
    attn_kernel<<<dim3(LQ / 128, Bz * Hh), 256, ATTN_SMEMB>>>(
        qkv, qkv + MROWS * Cc, qkv + 2 * MROWS * Cc, attn);

    // 4) self-attn out proj + residual + LN(ln2) -> t1, and qk2 = t1 + qpos
    gemm_tc<256,64,64,3><<<dim3(4, 64), 256, SMEMB(64,64,3)>>>(
        attn, nullptr, sa_w, sa_b, tmp, MROWS, Cc, 0, 0,
        nullptr, nullptr, nullptr, 0, 256, 256);
    add_ln_kernel<<<MROWS, 256>>>(tgt, tmp, ln2_g, ln2_b, qpos, t1, qk2);

    // 5+6) offsets + attention weights in one z-batched launch
    gemm_tc<256,64,64,3><<<dim3(4, 64, 2), 256, SMEMB(64,64,3)>>>(
        qk2, nullptr, off_w, off_b, off, MROWS, Cc, 0, 2,
        aw_w, aw_b, aw, 128, 256, 256);

    // join value projection, then deformable sampling
    cudaStreamWaitEvent(0, evJoin, 0);
    deform_kernel<<<(MROWS * Hh) / 4, 128>>>(val, off, aw, refp, attn);

    // 8) co proj + residual + LN(ln1) -> t2
    gemm_tc<256,64,64,3><<<dim3(4, 64), 256, SMEMB(64,64,3)>>>(
        attn, nullptr, co_w, co_b, tmp, MROWS, Cc, 0, 0,
        nullptr, nullptr, nullptr, 0, 256, 256);
    add_ln_kernel<<<MROWS, 256>>>(t1, tmp, ln1_g, ln1_b, nullptr, t2, nullptr);

    // 9) FFN: f1 (relu), f2 split-K over z=4, fused reduce+LN
    gemm_tc<256,128,64,3><<<dim3(16, 32), 256, SMEMB(128,64,3)>>>(
        t2, nullptr, f1_w, f1_b, ffn, MROWS, DFF, 1, 0,
        nullptr, nullptr, nullptr, 0, 256, 256);
    gemm_tc<256,64,64,3><<<dim3(4, 64, 4), 256, SMEMB(64,64,3)>>>(
        ffn, nullptr, f2_w, f2_b, part, MROWS, Cc, 0, 3,
        nullptr, zero, nullptr, 0, 1024, 1024);
    add_ln4_kernel<<<MROWS, 256>>>(t2, part, ln3_g, ln3_b, out);
}

// round 15
// speedup vs baseline: 1.1201x; 1.0353x over previous
#include <cuda_runtime.h>
#include <cuda_bf16.h>
#include <math.h>

#define Bz   4
#define LQ   1024
#define Cc   256
#define Hh   8
#define DH   32
#define DFF  1024
#define LSRC 21760
#define MROWS (Bz*LQ)        // 4096
#define VROWS (Bz*LSRC)      // 87040

// ---------------- scratch (static device globals) ---------------------------
__device__ float g_qk  [MROWS*Cc];
__device__ float g_qk2 [MROWS*Cc];
__device__ float g_qkv [3*MROWS*Cc];
__device__ float g_attn[MROWS*Cc];
__device__ float g_tmp [MROWS*Cc];
__device__ float g_tgt1[MROWS*Cc];
__device__ float g_tgt2[MROWS*Cc];
__device__ float g_off [MROWS*Cc];
__device__ float g_aw  [MROWS*128];
__device__ __nv_bfloat16 g_valb[VROWS*Cc];
__device__ float g_ffn [MROWS*DFF];
__device__ float g_part[4*MROWS*Cc];
__device__ float g_zero[DFF];          // zero-initialized

__device__ __forceinline__ unsigned pack_bf16(float lo, float hi) {
    unsigned r;
    asm("cvt.rn.bf16x2.f32 %0, %1, %2;" : "=r"(r) : "f"(hi), "f"(lo));
    return r;
}

#define MMA_TF32(C, A0,A1,A2,A3, B0,B1) \
    asm volatile("mma.sync.aligned.m16n8k8.row.col.f32.tf32.tf32.f32 " \
                 "{%0,%1,%2,%3}, {%4,%5,%6,%7}, {%8,%9}, {%0,%1,%2,%3};" \
                 : "+f"(C[0]), "+f"(C[1]), "+f"(C[2]), "+f"(C[3]) \
                 : "r"(A0), "r"(A1), "r"(A2), "r"(A3), "r"(B0), "r"(B1))

#define MMA_BF16(C, A0,A1,A2,A3, B0,B1) \
    asm volatile("mma.sync.aligned.m16n8k16.row.col.f32.bf16.bf16.f32 " \
                 "{%0,%1,%2,%3}, {%4,%5,%6,%7}, {%8,%9}, {%0,%1,%2,%3};" \
                 : "+f"(C[0]), "+f"(C[1]), "+f"(C[2]), "+f"(C[3]) \
                 : "r"(A0), "r"(A1), "r"(A2), "r"(A3), "r"(B0), "r"(B1))

// ---------------- elementwise add ------------------------------------------
__global__ void add_kernel(const float* __restrict__ a, const float* __restrict__ b,
                           float* __restrict__ y, int n)
{
    int i = blockIdx.x * 256 + threadIdx.x;
    if (i < n) y[i] = a[i] + b[i];
}

// ---------------- tf32 tensor-core GEMM, NSTG-stage cp.async pipeline -------
// mode 0: plain. mode 1: QKV batch over z. mode 2: off/aw pair. mode 3:
// split-K over z. If Ybf != nullptr, epilogue writes bf16 to Ybf instead.
#define GP 36
template<int K, int BM, int BN, int NSTG>
__global__ __launch_bounds__(256, 2)
void gemm_tc(const float* __restrict__ X, const float* __restrict__ Xalt,
             const float* __restrict__ W, const float* __restrict__ bias,
             float* __restrict__ Y, int M, int N, int relu, int mode,
             const float* __restrict__ W2, const float* __restrict__ b2,
             float* __restrict__ Y2, int N2, int ldx, int ldw,
             __nv_bfloat16* __restrict__ Ybf)
{
    extern __shared__ float smem[];
    constexpr int MT = BM / 32;
    constexpr int NT = BN / 32;
    constexpr int XTILE_F = BM * GP;
    constexpr int STAGE = (BM + BN) * GP;
    constexpr int NS = K >> 5;
    constexpr int TPRX = 256 / BM;
    constexpr int XG   = (32 / TPRX) / 4;
    constexpr int TPRW = 256 / BN;
    constexpr int WG   = (32 / TPRW) / 4;

    const int z = blockIdx.z;
    if (mode == 1 && z) {
        W    += (size_t)z * 256 * K;
        bias += z * 256;
        Y    += (size_t)z * M * N;
        if (z == 2) X = Xalt;
    } else if (mode == 2 && z) {
        if (blockIdx.x >= 2) return;
        W = W2; bias = b2; Y = Y2; N = N2;
    } else if (mode == 3) {
        X += z * K;
        W += z * K;
        Y += (size_t)z * M * N;
        if (z) bias = b2;
    }

    const int t    = threadIdx.x;
    const int warp = t >> 5;
    const int lane = t & 31;
    const int g    = lane >> 2;
    const int tg   = lane & 3;
    const int warp_m = warp >> 2;
    const int warp_n = warp & 3;
    const int m0 = blockIdx.y * BM;
    const int n0 = blockIdx.x * BN;

    const int xrow = t / TPRX;
    const int xcol = (t % TPRX) * (32 / TPRX);
    const int wrow = t / TPRW;
    const int wcol = (t % TPRW) * (32 / TPRW);

    float c[MT][NT][4];
#pragma unroll
    for (int i = 0; i < MT; i++)
#pragma unroll
        for (int j = 0; j < NT; j++)
#pragma unroll
            for (int r = 0; r < 4; r++) c[i][j][r] = 0.f;

    auto prefetch = [&](int s) {
        const int k0 = s << 5;
        float* xs = smem + (s % NSTG) * STAGE;
        float* ws = xs + XTILE_F;
        const float* gx = &X[(size_t)(m0 + xrow) * ldx + k0 + xcol];
        unsigned sx = (unsigned)__cvta_generic_to_shared(&xs[xrow * GP + xcol]);
#pragma unroll
        for (int q = 0; q < XG; q++)
            asm volatile("cp.async.cg.shared.global [%0], [%1], 16;\n"
                         :: "r"(sx + q * 16), "l"(gx + q * 4));
        const float* gw = &W[(size_t)(n0 + wrow) * ldw + k0 + wcol];
        unsigned sw = (unsigned)__cvta_generic_to_shared(&ws[wrow * GP + wcol]);
#pragma unroll
        for (int q = 0; q < WG; q++)
            asm volatile("cp.async.cg.shared.global [%0], [%1], 16;\n"
                         :: "r"(sw + q * 16), "l"(gw + q * 4));
        asm volatile("cp.async.commit_group;\n");
    };

#pragma unroll
    for (int i = 0; i < NSTG - 1; i++) prefetch(i);

#pragma unroll
    for (int s = 0; s < NS; s++) {
        if constexpr (NSTG == 2) {
            asm volatile("cp.async.wait_group 0;\n");
        } else {  // NSTG == 3
            if (s < NS - 1) asm volatile("cp.async.wait_group 1;\n");
            else            asm volatile("cp.async.wait_group 0;\n");
        }
        __syncthreads();
        if (s + NSTG - 1 < NS) prefetch(s + NSTG - 1);

        const float* xs = smem + (s % NSTG) * STAGE;
        const float* ws = xs + XTILE_F;

#pragma unroll
        for (int ks = 0; ks < 4; ks++) {
            const int kk = ks * 8;
            unsigned a[MT][4], b[NT][2];
#pragma unroll
            for (int mt = 0; mt < MT; mt++) {
                int rb = warp_m * (BM / 2) + mt * 16;
                a[mt][0] = __float_as_uint(xs[(rb + g    ) * GP + kk + tg    ]);
                a[mt][1] = __float_as_uint(xs[(rb + g + 8) * GP + kk + tg    ]);
                a[mt][2] = __float_as_uint(xs[(rb + g    ) * GP + kk + tg + 4]);
                a[mt][3] = __float_as_uint(xs[(rb + g + 8) * GP + kk + tg + 4]);
            }
#pragma unroll
            for (int nt = 0; nt < NT; nt++) {
                int nb = warp_n * (BN / 4) + nt * 8 + g;
                b[nt][0] = __float_as_uint(ws[nb * GP + kk + tg    ]);
                b[nt][1] = __float_as_uint(ws[nb * GP + kk + tg + 4]);
            }
#pragma unroll
            for (int mt = 0; mt < MT; mt++)
#pragma unroll
                for (int nt = 0; nt < NT; nt++)
                    MMA_TF32(c[mt][nt], a[mt][0], a[mt][1], a[mt][2], a[mt][3],
                             b[nt][0], b[nt][1]);
        }
    }

#pragma unroll
    for (int mt = 0; mt < MT; mt++) {
#pragma unroll
        for (int nt = 0; nt < NT; nt++) {
            int col = n0 + warp_n * (BN / 4) + nt * 8 + 2 * tg;
            float b0 = bias[col], b1 = bias[col + 1];
            int r0 = m0 + warp_m * (BM / 2) + mt * 16 + g;
            float v0 = c[mt][nt][0] + b0;
            float v1 = c[mt][nt][1] + b1;
            float v2 = c[mt][nt][2] + b0;
            float v3 = c[mt][nt][3] + b1;
            if (relu) {
                v0 = fmaxf(v0, 0.f); v1 = fmaxf(v1, 0.f);
                v2 = fmaxf(v2, 0.f); v3 = fmaxf(v3, 0.f);
            }
            if (Ybf) {
                *(unsigned*)&Ybf[(size_t)r0 * N + col]       = pack_bf16(v0, v1);
                *(unsigned*)&Ybf[(size_t)(r0 + 8) * N + col] = pack_bf16(v2, v3);
            } else {
                Y[(size_t)r0 * N + col]           = v0;
                Y[(size_t)r0 * N + col + 1]       = v1;
                Y[(size_t)(r0 + 8) * N + col]     = v2;
                Y[(size_t)(r0 + 8) * N + col + 1] = v3;
            }
        }
    }
}

#define SMEMB(BM,BN,NSTG) ((NSTG) * ((BM) + (BN)) * GP * 4)

// ---------------- residual + LayerNorm (row = 256) --------------------------
__global__ void add_ln_kernel(const float* __restrict__ A, const float* __restrict__ Bv,
                              const float* __restrict__ g, const float* __restrict__ be,
                              const float* __restrict__ qpos,
                              float* __restrict__ Y, float* __restrict__ Yq)
{
    int row = blockIdx.x, t = threadIdx.x;
    float x = A[(size_t)row * Cc + t] + Bv[(size_t)row * Cc + t];
    float s = x, s2 = x * x;
#pragma unroll
    for (int o = 16; o > 0; o >>= 1) {
        s  += __shfl_xor_sync(0xffffffffu, s, o);
        s2 += __shfl_xor_sync(0xffffffffu, s2, o);
    }
    __shared__ float ss[8], ss2[8];
    int w = t >> 5;
    if ((t & 31) == 0) { ss[w] = s; ss2[w] = s2; }
    __syncthreads();
    s = 0.f; s2 = 0.f;
#pragma unroll
    for (int i = 0; i < 8; i++) { s += ss[i]; s2 += ss2[i]; }
    float mean = s * (1.f / Cc);
    float var  = s2 * (1.f / Cc) - mean * mean;
    float inv  = rsqrtf(var + 1e-5f);
    float y = (x - mean) * inv * g[t] + be[t];
    Y[(size_t)row * Cc + t] = y;
    if (qpos) Yq[(size_t)row * Cc + t] = y + qpos[(size_t)row * Cc + t];
}

// residual + 4 split-K partials + LayerNorm
__global__ void add_ln4_kernel(const float* __restrict__ A, const float* __restrict__ P,
                               const float* __restrict__ g, const float* __restrict__ be,
                               float* __restrict__ Y)
{
    int row = blockIdx.x, t = threadIdx.x;
    size_t idx = (size_t)row * Cc + t;
    float x = A[idx] + P[idx] + P[idx + (size_t)MROWS*Cc]
            + P[idx + (size_t)2*MROWS*Cc] + P[idx + (size_t)3*MROWS*Cc];
    float s = x, s2 = x * x;
#pragma unroll
    for (int o = 16; o > 0; o >>= 1) {
        s  += __shfl_xor_sync(0xffffffffu, s, o);
        s2 += __shfl_xor_sync(0xffffffffu, s2, o);
    }
    __shared__ float ss[8], ss2[8];
    int w = t >> 5;
    if ((t & 31) == 0) { ss[w] = s; ss2[w] = s2; }
    __syncthreads();
    s = 0.f; s2 = 0.f;
#pragma unroll
    for (int i = 0; i < 8; i++) { s += ss[i]; s2 += ss2[i]; }
    float mean = s * (1.f / Cc);
    float var  = s2 * (1.f / Cc) - mean * mean;
    float inv  = rsqrtf(var + 1e-5f);
    Y[idx] = (x - mean) * inv * g[t] + be[t];
}

// ---------------- tensor-core flash attention (bf16 QK + bf16 PV) -----------
// grid (LQ/128, B*H), 256 thr. K and V staged through registers into bf16x2
// smem each chunk (double-buffered, one barrier per chunk). QK and PV both use
// m16n8k16 bf16 MMA with fp32 accumulation; softmax in fp32.
// Ksb pitch 20 u32 / Vt pitch 36 u32: fragment LDS banks all distinct.
#define KP 36
__global__ __launch_bounds__(256, 2)
void attn_kernel(const float* __restrict__ Q, const float* __restrict__ K,
                 const float* __restrict__ V, float* __restrict__ O)
{
    __shared__ float    Qs [128 * KP];
    __shared__ unsigned Ksb[2][64 * 20];
    __shared__ unsigned Vt [2][32 * 36];

    const int t = threadIdx.x;
    const int warp = t >> 5, lane = t & 31;
    const int g = lane >> 2, tg = lane & 3;
    const int bh = blockIdx.y;
    const int b = bh >> 3, h = bh & 7;
    const int q0 = blockIdx.x * 128;
    const size_t base = ((size_t)b * LQ) * Cc + h * DH;

    const int kkey = t & 63, kseg = t >> 6;   // K staging: key, 8-ch segment
    const int kp   = lane;                    // V staging: keypair
    const int ch0  = warp * 4;                // V staging: 4 channels

    // stage Q (scaled)
#pragma unroll
    for (int j = 0; j < 4; j++) {
        int idx = j * 256 + t;
        int row = idx >> 3, c4 = (idx & 7) * 4;
        float4 v4 = *(const float4*)&Q[base + (size_t)(q0 + row) * Cc + c4];
        v4.x *= 0.17677669529663687f; v4.y *= 0.17677669529663687f;
        v4.z *= 0.17677669529663687f; v4.w *= 0.17677669529663687f;
        *(float4*)&Qs[row * KP + c4] = v4;
    }

    // prologue: chunk-0 K and V into registers
    float4 kv0 = *(const float4*)&K[base + (size_t)kkey * Cc + kseg * 8];
    float4 kv1 = *(const float4*)&K[base + (size_t)kkey * Cc + kseg * 8 + 4];
    float4 vk0 = *(const float4*)&V[base + (size_t)(2 * kp)     * Cc + ch0];
    float4 vk1 = *(const float4*)&V[base + (size_t)(2 * kp + 1) * Cc + ch0];

    __syncthreads();   // Q staged

    // Q bf16 fragments: 2 k16-steps over dh=32
    unsigned qa[2][4];
    {
        int r = warp * 16 + g;
#pragma unroll
        for (int kt = 0; kt < 2; kt++) {
            qa[kt][0] = pack_bf16(Qs[r * KP + kt*16 + 2*tg],     Qs[r * KP + kt*16 + 2*tg + 1]);
            qa[kt][1] = pack_bf16(Qs[(r+8) * KP + kt*16 + 2*tg], Qs[(r+8) * KP + kt*16 + 2*tg + 1]);
            qa[kt][2] = pack_bf16(Qs[r * KP + kt*16 + 2*tg + 8], Qs[r * KP + kt*16 + 2*tg + 9]);
            qa[kt][3] = pack_bf16(Qs[(r+8) * KP + kt*16 + 2*tg + 8], Qs[(r+8) * KP + kt*16 + 2*tg + 9]);
        }
    }

    float o[4][4];
#pragma unroll
    for (int nt = 0; nt < 4; nt++)
#pragma unroll
        for (int r = 0; r < 4; r++) o[nt][r] = 0.f;
    float m0 = -1e30f, m1 = -1e30f, l0 = 0.f, l1 = 0.f;

#pragma unroll 1
    for (int c = 0; c < 16; c++) {
        const int buf = c & 1;

        // store K(c) as bf16x2 pairs along dh (pitch 20)
        {
            unsigned* dst = &Ksb[buf][kkey * 20 + kseg * 4];
            uint4 pk;
            pk.x = pack_bf16(kv0.x, kv0.y);
            pk.y = pack_bf16(kv0.z, kv0.w);
            pk.z = pack_bf16(kv1.x, kv1.y);
            pk.w = pack_bf16(kv1.z, kv1.w);
            *(uint4*)dst = pk;
        }
        // store V(c) as bf16x2 pairs along keys (pitch 36)
        Vt[buf][(ch0 + 0) * 36 + kp] = pack_bf16(vk0.x, vk1.x);
        Vt[buf][(ch0 + 1) * 36 + kp] = pack_bf16(vk0.y, vk1.y);
        Vt[buf][(ch0 + 2) * 36 + kp] = pack_bf16(vk0.z, vk1.z);
        Vt[buf][(ch0 + 3) * 36 + kp] = pack_bf16(vk0.w, vk1.w);

        __syncthreads();   // chunk c staged

        if (c < 15) {      // issue next-chunk loads (consumed next iteration)
            int c0n = (c + 1) * 64;
            kv0 = *(const float4*)&K[base + (size_t)(c0n + kkey) * Cc + kseg * 8];
            kv1 = *(const float4*)&K[base + (size_t)(c0n + kkey) * Cc + kseg * 8 + 4];
            vk0 = *(const float4*)&V[base + (size_t)(c0n + 2 * kp)     * Cc + ch0];
            vk1 = *(const float4*)&V[base + (size_t)(c0n + 2 * kp + 1) * Cc + ch0];
        }

        // S = Q @ K^T (bf16, fp32 accum)
        float c_[8][4];
#pragma unroll
        for (int nt = 0; nt < 8; nt++)
#pragma unroll
            for (int r = 0; r < 4; r++) c_[nt][r] = 0.f;
#pragma unroll
        for (int kt = 0; kt < 2; kt++) {
#pragma unroll
            for (int nt = 0; nt < 8; nt++) {
                unsigned b0 = Ksb[buf][(nt * 8 + g) * 20 + kt * 8 + tg];
                unsigned b1 = Ksb[buf][(nt * 8 + g) * 20 + kt * 8 + tg + 4];
                MMA_BF16(c_[nt], qa[kt][0], qa[kt][1], qa[kt][2], qa[kt][3], b0, b1);
            }
        }

        // online softmax (rows g, g+8; quad reductions)
        float mx0 = -1e30f, mx1 = -1e30f;
#pragma unroll
        for (int nt = 0; nt < 8; nt++) {
            mx0 = fmaxf(mx0, fmaxf(c_[nt][0], c_[nt][1]));
            mx1 = fmaxf(mx1, fmaxf(c_[nt][2], c_[nt][3]));
        }
        mx0 = fmaxf(mx0, __shfl_xor_sync(0xffffffffu, mx0, 1));
        mx0 = fmaxf(mx0, __shfl_xor_sync(0xffffffffu, mx0, 2));
        mx1 = fmaxf(mx1, __shfl_xor_sync(0xffffffffu, mx1, 1));
        mx1 = fmaxf(mx1, __shfl_xor_sync(0xffffffffu, mx1, 2));
        float mn0 = fmaxf(m0, mx0), mn1 = fmaxf(m1, mx1);
        float cor0 = __expf(m0 - mn0), cor1 = __expf(m1 - mn1);
        l0 *= cor0; l1 *= cor1;
#pragma unroll
        for (int nt = 0; nt < 4; nt++) {
            o[nt][0] *= cor0; o[nt][1] *= cor0;
            o[nt][2] *= cor1; o[nt][3] *= cor1;
        }
#pragma unroll
        for (int nt = 0; nt < 8; nt++) {
            c_[nt][0] = __expf(c_[nt][0] - mn0);
            c_[nt][1] = __expf(c_[nt][1] - mn0);
            c_[nt][2] = __expf(c_[nt][2] - mn1);
            c_[nt][3] = __expf(c_[nt][3] - mn1);
            l0 += c_[nt][0] + c_[nt][1];
            l1 += c_[nt][2] + c_[nt][3];
        }
        m0 = mn0; m1 = mn1;

        // O += P @ V (bf16; S C-fragment packs directly into PV A-fragment)
#pragma unroll
        for (int kt = 0; kt < 4; kt++) {
            unsigned a0 = pack_bf16(c_[2*kt  ][0], c_[2*kt  ][1]);
            unsigned a1 = pack_bf16(c_[2*kt  ][2], c_[2*kt  ][3]);
            unsigned a2 = pack_bf16(c_[2*kt+1][0], c_[2*kt+1][1]);
            unsigned a3 = pack_bf16(c_[2*kt+1][2], c_[2*kt+1][3]);
#pragma unroll
            for (int nt = 0; nt < 4; nt++) {
                unsigned b0 = Vt[buf][(8*nt + g) * 36 + 8*kt + tg];
                unsigned b1 = Vt[buf][(8*nt + g) * 36 + 8*kt + tg + 4];
                MMA_BF16(o[nt], a0, a1, a2, a3, b0, b1);
            }
        }
    }

    l0 += __shfl_xor_sync(0xffffffffu, l0, 1);
    l0 += __shfl_xor_sync(0xffffffffu, l0, 2);
    l1 += __shfl_xor_sync(0xffffffffu, l1, 1);
    l1 += __shfl_xor_sync(0xffffffffu, l1, 2);
    float inv0 = 1.f / l0, inv1 = 1.f / l1;

    int r0 = q0 + warp * 16 + g;
#pragma unroll
    for (int nt = 0; nt < 4; nt++) {
        int col = nt * 8 + 2 * tg;
        float2 w0 = make_float2(o[nt][0] * inv0, o[nt][1] * inv0);
        float2 w1 = make_float2(o[nt][2] * inv1, o[nt][3] * inv1);
        *(float2*)&O[base + (size_t)r0 * Cc + col]       = w0;
        *(float2*)&O[base + (size_t)(r0 + 8) * Cc + col] = w1;
    }
}

// ---------------- deformable sampling (warp per (b,q,h), lane = channel) ----
__global__ void deform_kernel(const __nv_bfloat16* __restrict__ val,
                              const float* __restrict__ offs,
                              const float* __restrict__ awl, const float* __restrict__ ref,
                              float* __restrict__ out)
{
    const int gid  = blockIdx.x * 4 + (threadIdx.x >> 5);
    const int lane = threadIdx.x & 31;
    const int h   = gid & 7;
    const int row = gid >> 3;
    const int b   = row >> 10;

    float a[16];
    float mx = -1e30f;
#pragma unroll
    for (int i = 0; i < 16; i++) {
        a[i] = awl[(size_t)row * 128 + h * 16 + i];
        mx = fmaxf(mx, a[i]);
    }
    float ssum = 0.f;
#pragma unroll
    for (int i = 0; i < 16; i++) { a[i] = __expf(a[i] - mx); ssum += a[i]; }
    float invs = 1.f / ssum;

    const int starts[4] = {0, 16384, 20480, 21504};
    float acc = 0.f;
#pragma unroll
    for (int lvl = 0; lvl < 4; lvl++) {
        const int Wl = 128 >> lvl;
        const int Hl = 128 >> lvl;
        const int start = starts[lvl];
        float rx = ref[((size_t)row * 4 + lvl) * 2 + 0];
        float ry = ref[((size_t)row * 4 + lvl) * 2 + 1];
#pragma unroll
        for (int p = 0; p < 4; p++) {
            size_t obase = (size_t)row * 256 + (((h * 4 + lvl) * 4 + p) * 2);
            float ox = offs[obase + 0];
            float oy = offs[obase + 1];
            float x = rx * (float)Wl + ox - 0.5f;
            float y = ry * (float)Hl + oy - 0.5f;
            float xf = floorf(x), yf = floorf(y);
            int x0 = (int)xf, y0 = (int)yf;
            float wx1 = x - xf, wx0 = 1.f - wx1;
            float wy1 = y - yf, wy0 = 1.f - wy1;
            float aw = a[lvl * 4 + p] * invs;

            float w00 = wx0 * wy0 * aw, w10 = wx1 * wy0 * aw;
            float w01 = wx0 * wy1 * aw, w11 = wx1 * wy1 * aw;
#pragma unroll
            for (int cidx = 0; cidx < 4; cidx++) {
                int ix = x0 + (cidx & 1);
                int iy = y0 + (cidx >> 1);
                float w = (cidx == 0) ? w00 : (cidx == 1) ? w10 : (cidx == 2) ? w01 : w11;
                if (ix >= 0 && ix < Wl && iy >= 0 && iy < Hl) {
                    size_t idx = (size_t)(b * LSRC + start + iy * Wl + ix) * Cc + h * DH + lane;
                    acc += w * __bfloat162float(val[idx]);
                }
            }
        }
    }
    out[(size_t)row * Cc + h * DH + lane] = acc;
}

// ---------------- launcher ---------------------------------------------------
extern "C" void kernel_launch(void* const* d_in, const int* in_sizes, int n_in,
                              void* d_out, int out_size)
{
    const float* tgt   = (const float*)d_in[0];
    const float* qpos  = (const float*)d_in[1];
    const float* refp  = (const float*)d_in[2];
    const float* src   = (const float*)d_in[3];
    const float* in_w  = (const float*)d_in[4];
    const float* in_b  = (const float*)d_in[5];
    const float* sa_w  = (const float*)d_in[6];
    const float* sa_b  = (const float*)d_in[7];
    const float* off_w = (const float*)d_in[8];
    const float* off_b = (const float*)d_in[9];
    const float* aw_w  = (const float*)d_in[10];
    const float* aw_b  = (const float*)d_in[11];
    const float* val_w = (const float*)d_in[12];
    const float* val_b = (const float*)d_in[13];
    const float* co_w  = (const float*)d_in[14];
    const float* co_b  = (const float*)d_in[15];
    const float* ln1_g = (const float*)d_in[16];
    const float* ln1_b = (const float*)d_in[17];
    const float* ln2_g = (const float*)d_in[18];
    const float* ln2_b = (const float*)d_in[19];
    const float* ln3_g = (const float*)d_in[20];
    const float* ln3_b = (const float*)d_in[21];
    const float* f1_w  = (const float*)d_in[22];
    const float* f1_b  = (const float*)d_in[23];
    const float* f2_w  = (const float*)d_in[24];
    const float* f2_b  = (const float*)d_in[25];
    float* out = (float*)d_out;

    float *qk, *qk2, *qkv, *attn, *tmp, *t1, *t2, *off, *aw, *ffn, *part, *zero;
    __nv_bfloat16* valb;
    cudaGetSymbolAddress((void**)&qk,   g_qk);
    cudaGetSymbolAddress((void**)&qk2,  g_qk2);
    cudaGetSymbolAddress((void**)&qkv,  g_qkv);
    cudaGetSymbolAddress((void**)&attn, g_attn);
    cudaGetSymbolAddress((void**)&tmp,  g_tmp);
    cudaGetSymbolAddress((void**)&t1,   g_tgt1);
    cudaGetSymbolAddress((void**)&t2,   g_tgt2);
    cudaGetSymbolAddress((void**)&off,  g_off);
    cudaGetSymbolAddress((void**)&aw,   g_aw);
    cudaGetSymbolAddress((void**)&valb, g_valb);
    cudaGetSymbolAddress((void**)&ffn,  g_ffn);
    cudaGetSymbolAddress((void**)&part, g_part);
    cudaGetSymbolAddress((void**)&zero, g_zero);

    static cudaStream_t s1;
    static cudaEvent_t evFork, evJoin;
    static int inited = 0;
    if (!inited) {
        cudaStreamCreateWithFlags(&s1, cudaStreamNonBlocking);
        cudaEventCreateWithFlags(&evFork, cudaEventDisableTiming);
        cudaEventCreateWithFlags(&evJoin, cudaEventDisableTiming);
        cudaFuncSetAttribute(gemm_tc<256,64,64,3>,
                             cudaFuncAttributeMaxDynamicSharedMemorySize, SMEMB(64,64,3));
        cudaFuncSetAttribute(gemm_tc<256,128,64,3>,
                             cudaFuncAttributeMaxDynamicSharedMemorySize, SMEMB(128,64,3));
        cudaFuncSetAttribute(gemm_tc<256,128,128,2>,
                             cudaFuncAttributeMaxDynamicSharedMemorySize, SMEMB(128,128,2));
        inited = 1;
    }

    const int NTOT = MROWS * Cc;

    // 1) qk = tgt + query_pos
    add_kernel<<<(NTOT + 255) / 256, 256>>>(tgt, qpos, qk, NTOT);

    // fork: value projection on side stream (bf16 output)
    cudaEventRecord(evFork, 0);
    cudaStreamWaitEvent(s1, evFork, 0);
    gemm_tc<256,128,128,2><<<dim3(2, VROWS / 128), 256, SMEMB(128,128,2), s1>>>(
        src, nullptr, val_w, val_b, nullptr, VROWS, Cc, 0, 0,
        nullptr, nullptr, nullptr, 0, 256, 256, valb);
    cudaEventRecord(evJoin, s1);

    // 2) Q/K/V projections — batched over grid.z
    gemm_tc<256,64,64,3><<<dim3(4, 64, 3), 256, SMEMB(64,64,3)>>>(
        qk, tgt, in_w, in_b, qkv, MROWS, Cc, 0, 1,
        nullptr, nullptr, nullptr, 0, 256, 256, nullptr);

    // 3) attention (bf16 QK + bf16 PV flash)
    attn_kernel<<<dim3(LQ / 128, Bz * Hh), 256>>>(
        qkv, qkv + MROWS * Cc, qkv + 2 * MROWS * Cc, attn);

    // 4) self-attn out proj + residual + LN(ln2) -> t1, and qk2 = t1 + qpos
    gemm_tc<256,64,64,3><<<dim3(4, 64), 256, SMEMB(64,64,3)>>>(
        attn, nullptr, sa_w, sa_b, tmp, MROWS, Cc, 0, 0,
        nullptr, nullptr, nullptr, 0, 256, 256, nullptr);
    add_ln_kernel<<<MROWS, 256>>>(tgt, tmp, ln2_g, ln2_b, qpos, t1, qk2);

    // 5+6) offsets + attention weights in one z-batched launch
    gemm_tc<256,64,64,3><<<dim3(4, 64, 2), 256, SMEMB(64,64,3)>>>(
        qk2, nullptr, off_w, off_b, off, MROWS, Cc, 0, 2,
        aw_w, aw_b, aw, 128, 256, 256, nullptr);

    // join value projection, then deformable sampling
    cudaStreamWaitEvent(0, evJoin, 0);
    deform_kernel<<<(MROWS * Hh) / 4, 128>>>(valb, off, aw, refp, attn);

    // 8) co proj + residual + LN(ln1) -> t2
    gemm_tc<256,64,64,3><<<dim3(4, 64), 256, SMEMB(64,64,3)>>>(
        attn, nullptr, co_w, co_b, tmp, MROWS, Cc, 0, 0,
        nullptr, nullptr, nullptr, 0, 256, 256, nullptr);
    add_ln_kernel<<<MROWS, 256>>>(t1, tmp, ln1_g, ln1_b, nullptr, t2, nullptr);

    // 9) FFN: f1 (relu), f2 split-K over z=4, fused reduce+LN
    gemm_tc<256,128,64,3><<<dim3(16, 32), 256, SMEMB(128,64,3)>>>(
        t2, nullptr, f1_w, f1_b, ffn, MROWS, DFF, 1, 0,
        nullptr, nullptr, nullptr, 0, 256, 256, nullptr);
    gemm_tc<256,64,64,3><<<dim3(4, 64, 4), 256, SMEMB(64,64,3)>>>(
        ffn, nullptr, f2_w, f2_b, part, MROWS, Cc, 0, 3,
        nullptr, zero, nullptr, 0, 1024, 1024, nullptr);
    add_ln4_kernel<<<MROWS, 256>>>(t2, part, ln3_g, ln3_b, out);
}

// round 16
// speedup vs baseline: 1.1542x; 1.0305x over previous
#include <cuda_runtime.h>
#include <cuda_bf16.h>
#include <math.h>

#define Bz   4
#define LQ   1024
#define Cc   256
#define Hh   8
#define DH   32
#define DFF  1024
#define LSRC 21760
#define MROWS (Bz*LQ)        // 4096
#define VROWS (Bz*LSRC)      // 87040

// ---------------- scratch (static device globals) ---------------------------
__device__ float g_qk  [MROWS*Cc];
__device__ float g_qk2 [MROWS*Cc];
__device__ float g_qkv [MROWS*Cc];             // Q (fp32)
__device__ __nv_bfloat16 g_kvb[2*MROWS*Cc];    // K, V (bf16)
__device__ float g_attn[MROWS*Cc];
__device__ float g_tmp [MROWS*Cc];
__device__ float g_tgt1[MROWS*Cc];
__device__ float g_tgt2[MROWS*Cc];
__device__ float g_off [MROWS*Cc];
__device__ float g_aw  [MROWS*128];
__device__ __nv_bfloat16 g_valb[VROWS*Cc];
__device__ float g_ffn [MROWS*DFF];
__device__ float g_part[4*MROWS*Cc];
__device__ float g_zero[DFF];                  // zero-initialized

__device__ __forceinline__ unsigned pack_bf16(float lo, float hi) {
    unsigned r;
    asm("cvt.rn.bf16x2.f32 %0, %1, %2;" : "=r"(r) : "f"(hi), "f"(lo));
    return r;
}

#define MMA_TF32(C, A0,A1,A2,A3, B0,B1) \
    asm volatile("mma.sync.aligned.m16n8k8.row.col.f32.tf32.tf32.f32 " \
                 "{%0,%1,%2,%3}, {%4,%5,%6,%7}, {%8,%9}, {%0,%1,%2,%3};" \
                 : "+f"(C[0]), "+f"(C[1]), "+f"(C[2]), "+f"(C[3]) \
                 : "r"(A0), "r"(A1), "r"(A2), "r"(A3), "r"(B0), "r"(B1))

#define MMA_BF16(C, A0,A1,A2,A3, B0,B1) \
    asm volatile("mma.sync.aligned.m16n8k16.row.col.f32.bf16.bf16.f32 " \
                 "{%0,%1,%2,%3}, {%4,%5,%6,%7}, {%8,%9}, {%0,%1,%2,%3};" \
                 : "+f"(C[0]), "+f"(C[1]), "+f"(C[2]), "+f"(C[3]) \
                 : "r"(A0), "r"(A1), "r"(A2), "r"(A3), "r"(B0), "r"(B1))

// ---------------- elementwise add ------------------------------------------
__global__ void add_kernel(const float* __restrict__ a, const float* __restrict__ b,
                           float* __restrict__ y, int n)
{
    int i = blockIdx.x * 256 + threadIdx.x;
    if (i < n) y[i] = a[i] + b[i];
}

// ---------------- tf32 tensor-core GEMM, NSTG-stage cp.async pipeline -------
// mode 0: plain. mode 1: QKV batch over z (z==0 -> fp32 Y; z>=1 -> bf16 Ybf
// slice z-1). mode 2: off/aw pair. mode 3: split-K over z.
// In modes 0/2/3, Ybf != nullptr redirects the whole output to bf16.
#define GP 36
template<int K, int BM, int BN, int NSTG>
__global__ __launch_bounds__(256, 2)
void gemm_tc(const float* __restrict__ X, const float* __restrict__ Xalt,
             const float* __restrict__ W, const float* __restrict__ bias,
             float* __restrict__ Y, int M, int N, int relu, int mode,
             const float* __restrict__ W2, const float* __restrict__ b2,
             float* __restrict__ Y2, int N2, int ldx, int ldw,
             __nv_bfloat16* __restrict__ Ybf)
{
    extern __shared__ float smem[];
    constexpr int MT = BM / 32;
    constexpr int NT = BN / 32;
    constexpr int XTILE_F = BM * GP;
    constexpr int STAGE = (BM + BN) * GP;
    constexpr int NS = K >> 5;
    constexpr int TPRX = 256 / BM;
    constexpr int XG   = (32 / TPRX) / 4;
    constexpr int TPRW = 256 / BN;
    constexpr int WG   = (32 / TPRW) / 4;

    const int z = blockIdx.z;
    if (mode == 1) {
        if (z) {
            W    += (size_t)z * 256 * K;
            bias += z * 256;
            Ybf  += (size_t)(z - 1) * M * N;
            if (z == 2) X = Xalt;
        } else {
            Ybf = nullptr;
        }
    } else if (mode == 2 && z) {
        if (blockIdx.x >= 2) return;
        W = W2; bias = b2; Y = Y2; N = N2;
    } else if (mode == 3) {
        X += z * K;
        W += z * K;
        Y += (size_t)z * M * N;
        if (z) bias = b2;
    }

    const int t    = threadIdx.x;
    const int warp = t >> 5;
    const int lane = t & 31;
    const int g    = lane >> 2;
    const int tg   = lane & 3;
    const int warp_m = warp >> 2;
    const int warp_n = warp & 3;
    const int m0 = blockIdx.y * BM;
    const int n0 = blockIdx.x * BN;

    const int xrow = t / TPRX;
    const int xcol = (t % TPRX) * (32 / TPRX);
    const int wrow = t / TPRW;
    const int wcol = (t % TPRW) * (32 / TPRW);

    float c[MT][NT][4];
#pragma unroll
    for (int i = 0; i < MT; i++)
#pragma unroll
        for (int j = 0; j < NT; j++)
#pragma unroll
            for (int r = 0; r < 4; r++) c[i][j][r] = 0.f;

    auto prefetch = [&](int s) {
        const int k0 = s << 5;
        float* xs = smem + (s % NSTG) * STAGE;
        float* ws = xs + XTILE_F;
        const float* gx = &X[(size_t)(m0 + xrow) * ldx + k0 + xcol];
        unsigned sx = (unsigned)__cvta_generic_to_shared(&xs[xrow * GP + xcol]);
#pragma unroll
        for (int q = 0; q < XG; q++)
            asm volatile("cp.async.cg.shared.global [%0], [%1], 16;\n"
                         :: "r"(sx + q * 16), "l"(gx + q * 4));
        const float* gw = &W[(size_t)(n0 + wrow) * ldw + k0 + wcol];
        unsigned sw = (unsigned)__cvta_generic_to_shared(&ws[wrow * GP + wcol]);
#pragma unroll
        for (int q = 0; q < WG; q++)
            asm volatile("cp.async.cg.shared.global [%0], [%1], 16;\n"
                         :: "r"(sw + q * 16), "l"(gw + q * 4));
        asm volatile("cp.async.commit_group;\n");
    };

#pragma unroll
    for (int i = 0; i < NSTG - 1; i++) prefetch(i);

#pragma unroll
    for (int s = 0; s < NS; s++) {
        if constexpr (NSTG == 2) {
            asm volatile("cp.async.wait_group 0;\n");
        } else {  // NSTG == 3
            if (s < NS - 1) asm volatile("cp.async.wait_group 1;\n");
            else            asm volatile("cp.async.wait_group 0;\n");
        }
        __syncthreads();
        if (s + NSTG - 1 < NS) prefetch(s + NSTG - 1);

        const float* xs = smem + (s % NSTG) * STAGE;
        const float* ws = xs + XTILE_F;

#pragma unroll
        for (int ks = 0; ks < 4; ks++) {
            const int kk = ks * 8;
            unsigned a[MT][4], b[NT][2];
#pragma unroll
            for (int mt = 0; mt < MT; mt++) {
                int rb = warp_m * (BM / 2) + mt * 16;
                a[mt][0] = __float_as_uint(xs[(rb + g    ) * GP + kk + tg    ]);
                a[mt][1] = __float_as_uint(xs[(rb + g + 8) * GP + kk + tg    ]);
                a[mt][2] = __float_as_uint(xs[(rb + g    ) * GP + kk + tg + 4]);
                a[mt][3] = __float_as_uint(xs[(rb + g + 8) * GP + kk + tg + 4]);
            }
#pragma unroll
            for (int nt = 0; nt < NT; nt++) {
                int nb = warp_n * (BN / 4) + nt * 8 + g;
                b[nt][0] = __float_as_uint(ws[nb * GP + kk + tg    ]);
                b[nt][1] = __float_as_uint(ws[nb * GP + kk + tg + 4]);
            }
#pragma unroll
            for (int mt = 0; mt < MT; mt++)
#pragma unroll
                for (int nt = 0; nt < NT; nt++)
                    MMA_TF32(c[mt][nt], a[mt][0], a[mt][1], a[mt][2], a[mt][3],
                             b[nt][0], b[nt][1]);
        }
    }

#pragma unroll
    for (int mt = 0; mt < MT; mt++) {
#pragma unroll
        for (int nt = 0; nt < NT; nt++) {
            int col = n0 + warp_n * (BN / 4) + nt * 8 + 2 * tg;
            float b0 = bias[col], b1 = bias[col + 1];
            int r0 = m0 + warp_m * (BM / 2) + mt * 16 + g;
            float v0 = c[mt][nt][0] + b0;
            float v1 = c[mt][nt][1] + b1;
            float v2 = c[mt][nt][2] + b0;
            float v3 = c[mt][nt][3] + b1;
            if (relu) {
                v0 = fmaxf(v0, 0.f); v1 = fmaxf(v1, 0.f);
                v2 = fmaxf(v2, 0.f); v3 = fmaxf(v3, 0.f);
            }
            if (Ybf) {
                *(unsigned*)&Ybf[(size_t)r0 * N + col]       = pack_bf16(v0, v1);
                *(unsigned*)&Ybf[(size_t)(r0 + 8) * N + col] = pack_bf16(v2, v3);
            } else {
                Y[(size_t)r0 * N + col]           = v0;
                Y[(size_t)r0 * N + col + 1]       = v1;
                Y[(size_t)(r0 + 8) * N + col]     = v2;
                Y[(size_t)(r0 + 8) * N + col + 1] = v3;
            }
        }
    }
}

#define SMEMB(BM,BN,NSTG) ((NSTG) * ((BM) + (BN)) * GP * 4)

// ---------------- residual + LayerNorm (row = 256) --------------------------
__global__ void add_ln_kernel(const float* __restrict__ A, const float* __restrict__ Bv,
                              const float* __restrict__ g, const float* __restrict__ be,
                              const float* __restrict__ qpos,
                              float* __restrict__ Y, float* __restrict__ Yq)
{
    int row = blockIdx.x, t = threadIdx.x;
    float x = A[(size_t)row * Cc + t] + Bv[(size_t)row * Cc + t];
    float s = x, s2 = x * x;
#pragma unroll
    for (int o = 16; o > 0; o >>= 1) {
        s  += __shfl_xor_sync(0xffffffffu, s, o);
        s2 += __shfl_xor_sync(0xffffffffu, s2, o);
    }
    __shared__ float ss[8], ss2[8];
    int w = t >> 5;
    if ((t & 31) == 0) { ss[w] = s; ss2[w] = s2; }
    __syncthreads();
    s = 0.f; s2 = 0.f;
#pragma unroll
    for (int i = 0; i < 8; i++) { s += ss[i]; s2 += ss2[i]; }
    float mean = s * (1.f / Cc);
    float var  = s2 * (1.f / Cc) - mean * mean;
    float inv  = rsqrtf(var + 1e-5f);
    float y = (x - mean) * inv * g[t] + be[t];
    Y[(size_t)row * Cc + t] = y;
    if (qpos) Yq[(size_t)row * Cc + t] = y + qpos[(size_t)row * Cc + t];
}

// residual + 4 split-K partials + LayerNorm
__global__ void add_ln4_kernel(const float* __restrict__ A, const float* __restrict__ P,
                               const float* __restrict__ g, const float* __restrict__ be,
                               float* __restrict__ Y)
{
    int row = blockIdx.x, t = threadIdx.x;
    size_t idx = (size_t)row * Cc + t;
    float x = A[idx] + P[idx] + P[idx + (size_t)MROWS*Cc]
            + P[idx + (size_t)2*MROWS*Cc] + P[idx + (size_t)3*MROWS*Cc];
    float s = x, s2 = x * x;
#pragma unroll
    for (int o = 16; o > 0; o >>= 1) {
        s  += __shfl_xor_sync(0xffffffffu, s, o);
        s2 += __shfl_xor_sync(0xffffffffu, s2, o);
    }
    __shared__ float ss[8], ss2[8];
    int w = t >> 5;
    if ((t & 31) == 0) { ss[w] = s; ss2[w] = s2; }
    __syncthreads();
    s = 0.f; s2 = 0.f;
#pragma unroll
    for (int i = 0; i < 8; i++) { s += ss[i]; s2 += ss2[i]; }
    float mean = s * (1.f / Cc);
    float var  = s2 * (1.f / Cc) - mean * mean;
    float inv  = rsqrtf(var + 1e-5f);
    Y[idx] = (x - mean) * inv * g[t] + be[t];
}

// ---------------- tensor-core flash attention (bf16 QK + bf16 PV) -----------
// K/V arrive already in bf16. K chunks: cp.async double-buffer straight into
// the bf16x2 pair layout (row-major bf16 IS pair order). V: 8-byte register
// loads + byte_perm interleave into Vt[ch][keypair]. One barrier per chunk.
#define KP 36
__global__ __launch_bounds__(256, 2)
void attn_kernel(const float* __restrict__ Q, const __nv_bfloat16* __restrict__ Kb,
                 const __nv_bfloat16* __restrict__ Vb, float* __restrict__ O)
{
    __shared__ float    Qs [128 * KP];
    __shared__ unsigned Ksb[2][64 * 20];
    __shared__ unsigned Vt [2][32 * 36];

    const int t = threadIdx.x;
    const int warp = t >> 5, lane = t & 31;
    const int g = lane >> 2, tg = lane & 3;
    const int bh = blockIdx.y;
    const int b = bh >> 3, h = bh & 7;
    const int q0 = blockIdx.x * 128;
    const size_t base = ((size_t)b * LQ) * Cc + h * DH;

    const int kkey = t & 63, kseg = t >> 6;   // K: key, 8-channel segment
    const int kp   = lane;                    // V: keypair
    const int ch0  = warp * 4;                // V: 4 channels

    auto prefetchK = [&](int c0, int buf) {
        const __nv_bfloat16* src = &Kb[base + (size_t)(c0 + kkey) * Cc + kseg * 8];
        unsigned dst = (unsigned)__cvta_generic_to_shared(&Ksb[buf][kkey * 20 + kseg * 4]);
        asm volatile("cp.async.cg.shared.global [%0], [%1], 16;\n"
                     :: "r"(dst), "l"(src));
        asm volatile("cp.async.commit_group;\n");
    };

    // stage Q (scaled, fp32)
#pragma unroll
    for (int j = 0; j < 4; j++) {
        int idx = j * 256 + t;
        int row = idx >> 3, c4 = (idx & 7) * 4;
        float4 v4 = *(const float4*)&Q[base + (size_t)(q0 + row) * Cc + c4];
        v4.x *= 0.17677669529663687f; v4.y *= 0.17677669529663687f;
        v4.z *= 0.17677669529663687f; v4.w *= 0.17677669529663687f;
        *(float4*)&Qs[row * KP + c4] = v4;
    }

    // prologue: K chunk 0 via cp.async, V chunk 0 into registers
    prefetchK(0, 0);
    uint2 va = *(const uint2*)&Vb[base + (size_t)(2 * kp)     * Cc + ch0];
    uint2 vb = *(const uint2*)&Vb[base + (size_t)(2 * kp + 1) * Cc + ch0];

    __syncthreads();   // Q staged

    // Q bf16 fragments: 2 k16-steps over dh=32
    unsigned qa[2][4];
    {
        int r = warp * 16 + g;
#pragma unroll
        for (int kt = 0; kt < 2; kt++) {
            qa[kt][0] = pack_bf16(Qs[r * KP + kt*16 + 2*tg],     Qs[r * KP + kt*16 + 2*tg + 1]);
            qa[kt][1] = pack_bf16(Qs[(r+8) * KP + kt*16 + 2*tg], Qs[(r+8) * KP + kt*16 + 2*tg + 1]);
            qa[kt][2] = pack_bf16(Qs[r * KP + kt*16 + 2*tg + 8], Qs[r * KP + kt*16 + 2*tg + 9]);
            qa[kt][3] = pack_bf16(Qs[(r+8) * KP + kt*16 + 2*tg + 8], Qs[(r+8) * KP + kt*16 + 2*tg + 9]);
        }
    }

    float o[4][4];
#pragma unroll
    for (int nt = 0; nt < 4; nt++)
#pragma unroll
        for (int r = 0; r < 4; r++) o[nt][r] = 0.f;
    float m0 = -1e30f, m1 = -1e30f, l0 = 0.f, l1 = 0.f;

#pragma unroll 1
    for (int c = 0; c < 16; c++) {
        const int buf = c & 1;

        // store V(c): interleave key pair via byte_perm
        Vt[buf][(ch0 + 0) * 36 + kp] = __byte_perm(va.x, vb.x, 0x5410);
        Vt[buf][(ch0 + 1) * 36 + kp] = __byte_perm(va.x, vb.x, 0x7632);
        Vt[buf][(ch0 + 2) * 36 + kp] = __byte_perm(va.y, vb.y, 0x5410);
        Vt[buf][(ch0 + 3) * 36 + kp] = __byte_perm(va.y, vb.y, 0x7632);

        asm volatile("cp.async.wait_group 0;\n");
        __syncthreads();   // Ks[buf] arrived, Vt[buf] stored

        if (c < 15) {      // issue next-chunk loads (consumed next iteration)
            int c0n = (c + 1) * 64;
            prefetchK(c0n, buf ^ 1);
            va = *(const uint2*)&Vb[base + (size_t)(c0n + 2 * kp)     * Cc + ch0];
            vb = *(const uint2*)&Vb[base + (size_t)(c0n + 2 * kp + 1) * Cc + ch0];
        }

        // S = Q @ K^T (bf16, fp32 accum)
        float c_[8][4];
#pragma unroll
        for (int nt = 0; nt < 8; nt++)
#pragma unroll
            for (int r = 0; r < 4; r++) c_[nt][r] = 0.f;
#pragma unroll
        for (int kt = 0; kt < 2; kt++) {
#pragma unroll
            for (int nt = 0; nt < 8; nt++) {
                unsigned b0 = Ksb[buf][(nt * 8 + g) * 20 + kt * 8 + tg];
                unsigned b1 = Ksb[buf][(nt * 8 + g) * 20 + kt * 8 + tg + 4];
                MMA_BF16(c_[nt], qa[kt][0], qa[kt][1], qa[kt][2], qa[kt][3], b0, b1);
            }
        }

        // online softmax (rows g, g+8; quad reductions)
        float mx0 = -1e30f, mx1 = -1e30f;
#pragma unroll
        for (int nt = 0; nt < 8; nt++) {
            mx0 = fmaxf(mx0, fmaxf(c_[nt][0], c_[nt][1]));
            mx1 = fmaxf(mx1, fmaxf(c_[nt][2], c_[nt][3]));
        }
        mx0 = fmaxf(mx0, __shfl_xor_sync(0xffffffffu, mx0, 1));
        mx0 = fmaxf(mx0, __shfl_xor_sync(0xffffffffu, mx0, 2));
        mx1 = fmaxf(mx1, __shfl_xor_sync(0xffffffffu, mx1, 1));
        mx1 = fmaxf(mx1, __shfl_xor_sync(0xffffffffu, mx1, 2));
        float mn0 = fmaxf(m0, mx0), mn1 = fmaxf(m1, mx1);
        float cor0 = __expf(m0 - mn0), cor1 = __expf(m1 - mn1);
        l0 *= cor0; l1 *= cor1;
#pragma unroll
        for (int nt = 0; nt < 4; nt++) {
            o[nt][0] *= cor0; o[nt][1] *= cor0;
            o[nt][2] *= cor1; o[nt][3] *= cor1;
        }
#pragma unroll
        for (int nt = 0; nt < 8; nt++) {
            c_[nt][0] = __expf(c_[nt][0] - mn0);
            c_[nt][1] = __expf(c_[nt][1] - mn0);
            c_[nt][2] = __expf(c_[nt][2] - mn1);
            c_[nt][3] = __expf(c_[nt][3] - mn1);
            l0 += c_[nt][0] + c_[nt][1];
            l1 += c_[nt][2] + c_[nt][3];
        }
        m0 = mn0; m1 = mn1;

        // O += P @ V (bf16; S C-fragment packs directly into PV A-fragment)
#pragma unroll
        for (int kt = 0; kt < 4; kt++) {
            unsigned a0 = pack_bf16(c_[2*kt  ][0], c_[2*kt  ][1]);
            unsigned a1 = pack_bf16(c_[2*kt  ][2], c_[2*kt  ][3]);
            unsigned a2 = pack_bf16(c_[2*kt+1][0], c_[2*kt+1][1]);
            unsigned a3 = pack_bf16(c_[2*kt+1][2], c_[2*kt+1][3]);
#pragma unroll
            for (int nt = 0; nt < 4; nt++) {
                unsigned b0 = Vt[buf][(8*nt + g) * 36 + 8*kt + tg];
                unsigned b1 = Vt[buf][(8*nt + g) * 36 + 8*kt + tg + 4];
                MMA_BF16(o[nt], a0, a1, a2, a3, b0, b1);
            }
        }
    }

    l0 += __shfl_xor_sync(0xffffffffu, l0, 1);
    l0 += __shfl_xor_sync(0xffffffffu, l0, 2);
    l1 += __shfl_xor_sync(0xffffffffu, l1, 1);
    l1 += __shfl_xor_sync(0xffffffffu, l1, 2);
    float inv0 = 1.f / l0, inv1 = 1.f / l1;

    int r0 = q0 + warp * 16 + g;
#pragma unroll
    for (int nt = 0; nt < 4; nt++) {
        int col = nt * 8 + 2 * tg;
        float2 w0 = make_float2(o[nt][0] * inv0, o[nt][1] * inv0);
        float2 w1 = make_float2(o[nt][2] * inv1, o[nt][3] * inv1);
        *(float2*)&O[base + (size_t)r0 * Cc + col]       = w0;
        *(float2*)&O[base + (size_t)(r0 + 8) * Cc + col] = w1;
    }
}

// ---------------- deformable sampling (warp per (b,q,h), lane = channel) ----
__global__ void deform_kernel(const __nv_bfloat16* __restrict__ val,
                              const float* __restrict__ offs,
                              const float* __restrict__ awl, const float* __restrict__ ref,
                              float* __restrict__ out)
{
    const int gid  = blockIdx.x * 4 + (threadIdx.x >> 5);
    const int lane = threadIdx.x & 31;
    const int h   = gid & 7;
    const int row = gid >> 3;
    const int b   = row >> 10;

    float a[16];
    float mx = -1e30f;
#pragma unroll
    for (int i = 0; i < 16; i++) {
        a[i] = awl[(size_t)row * 128 + h * 16 + i];
        mx = fmaxf(mx, a[i]);
    }
    float ssum = 0.f;
#pragma unroll
    for (int i = 0; i < 16; i++) { a[i] = __expf(a[i] - mx); ssum += a[i]; }
    float invs = 1.f / ssum;

    const int starts[4] = {0, 16384, 20480, 21504};
    float acc = 0.f;
#pragma unroll
    for (int lvl = 0; lvl < 4; lvl++) {
        const int Wl = 128 >> lvl;
        const int Hl = 128 >> lvl;
        const int start = starts[lvl];
        float rx = ref[((size_t)row * 4 + lvl) * 2 + 0];
        float ry = ref[((size_t)row * 4 + lvl) * 2 + 1];
#pragma unroll
        for (int p = 0; p < 4; p++) {
            size_t obase = (size_t)row * 256 + (((h * 4 + lvl) * 4 + p) * 2);
            float ox = offs[obase + 0];
            float oy = offs[obase + 1];
            float x = rx * (float)Wl + ox - 0.5f;
            float y = ry * (float)Hl + oy - 0.5f;
            float xf = floorf(x), yf = floorf(y);
            int x0 = (int)xf, y0 = (int)yf;
            float wx1 = x - xf, wx0 = 1.f - wx1;
            float wy1 = y - yf, wy0 = 1.f - wy1;
            float aw = a[lvl * 4 + p] * invs;

            float w00 = wx0 * wy0 * aw, w10 = wx1 * wy0 * aw;
            float w01 = wx0 * wy1 * aw, w11 = wx1 * wy1 * aw;
#pragma unroll
            for (int cidx = 0; cidx < 4; cidx++) {
                int ix = x0 + (cidx & 1);
                int iy = y0 + (cidx >> 1);
                float w = (cidx == 0) ? w00 : (cidx == 1) ? w10 : (cidx == 2) ? w01 : w11;
                if (ix >= 0 && ix < Wl && iy >= 0 && iy < Hl) {
                    size_t idx = (size_t)(b * LSRC + start + iy * Wl + ix) * Cc + h * DH + lane;
                    acc += w * __bfloat162float(val[idx]);
                }
            }
        }
    }
    out[(size_t)row * Cc + h * DH + lane] = acc;
}

// ---------------- launcher ---------------------------------------------------
extern "C" void kernel_launch(void* const* d_in, const int* in_sizes, int n_in,
                              void* d_out, int out_size)
{
    const float* tgt   = (const float*)d_in[0];
    const float* qpos  = (const float*)d_in[1];
    const float* refp  = (const float*)d_in[2];
    const float* src   = (const float*)d_in[3];
    const float* in_w  = (const float*)d_in[4];
    const float* in_b  = (const float*)d_in[5];
    const float* sa_w  = (const float*)d_in[6];
    const float* sa_b  = (const float*)d_in[7];
    const float* off_w = (const float*)d_in[8];
    const float* off_b = (const float*)d_in[9];
    const float* aw_w  = (const float*)d_in[10];
    const float* aw_b  = (const float*)d_in[11];
    const float* val_w = (const float*)d_in[12];
    const float* val_b = (const float*)d_in[13];
    const float* co_w  = (const float*)d_in[14];
    const float* co_b  = (const float*)d_in[15];
    const float* ln1_g = (const float*)d_in[16];
    const float* ln1_b = (const float*)d_in[17];
    const float* ln2_g = (const float*)d_in[18];
    const float* ln2_b = (const float*)d_in[19];
    const float* ln3_g = (const float*)d_in[20];
    const float* ln3_b = (const float*)d_in[21];
    const float* f1_w  = (const float*)d_in[22];
    const float* f1_b  = (const float*)d_in[23];
    const float* f2_w  = (const float*)d_in[24];
    const float* f2_b  = (const float*)d_in[25];
    float* out = (float*)d_out;

    float *qk, *qk2, *qkv, *attn, *tmp, *t1, *t2, *off, *aw, *ffn, *part, *zero;
    __nv_bfloat16 *valb, *kvb;
    cudaGetSymbolAddress((void**)&qk,   g_qk);
    cudaGetSymbolAddress((void**)&qk2,  g_qk2);
    cudaGetSymbolAddress((void**)&qkv,  g_qkv);
    cudaGetSymbolAddress((void**)&kvb,  g_kvb);
    cudaGetSymbolAddress((void**)&attn, g_attn);
    cudaGetSymbolAddress((void**)&tmp,  g_tmp);
    cudaGetSymbolAddress((void**)&t1,   g_tgt1);
    cudaGetSymbolAddress((void**)&t2,   g_tgt2);
    cudaGetSymbolAddress((void**)&off,  g_off);
    cudaGetSymbolAddress((void**)&aw,   g_aw);
    cudaGetSymbolAddress((void**)&valb, g_valb);
    cudaGetSymbolAddress((void**)&ffn,  g_ffn);
    cudaGetSymbolAddress((void**)&part, g_part);
    cudaGetSymbolAddress((void**)&zero, g_zero);

    static cudaStream_t s1;
    static cudaEvent_t evFork, evJoin;
    static int inited = 0;
    if (!inited) {
        cudaStreamCreateWithFlags(&s1, cudaStreamNonBlocking);
        cudaEventCreateWithFlags(&evFork, cudaEventDisableTiming);
        cudaEventCreateWithFlags(&evJoin, cudaEventDisableTiming);
        cudaFuncSetAttribute(gemm_tc<256,64,64,3>,
                             cudaFuncAttributeMaxDynamicSharedMemorySize, SMEMB(64,64,3));
        cudaFuncSetAttribute(gemm_tc<256,128,64,3>,
                             cudaFuncAttributeMaxDynamicSharedMemorySize, SMEMB(128,64,3));
        cudaFuncSetAttribute(gemm_tc<256,128,128,2>,
                             cudaFuncAttributeMaxDynamicSharedMemorySize, SMEMB(128,128,2));
        inited = 1;
    }

    const int NTOT = MROWS * Cc;

    // 1) qk = tgt + query_pos
    add_kernel<<<(NTOT + 255) / 256, 256>>>(tgt, qpos, qk, NTOT);

    // fork: value projection on side stream (bf16 output)
    cudaEventRecord(evFork, 0);
    cudaStreamWaitEvent(s1, evFork, 0);
    gemm_tc<256,128,128,2><<<dim3(2, VROWS / 128), 256, SMEMB(128,128,2), s1>>>(
        src, nullptr, val_w, val_b, nullptr, VROWS, Cc, 0, 0,
        nullptr, nullptr, nullptr, 0, 256, 256, valb);
    cudaEventRecord(evJoin, s1);

    // 2) Q/K/V projections — Q fp32, K/V bf16
    gemm_tc<256,64,64,3><<<dim3(4, 64, 3), 256, SMEMB(64,64,3)>>>(
        qk, tgt, in_w, in_b, qkv, MROWS, Cc, 0, 1,
        nullptr, nullptr, nullptr, 0, 256, 256, kvb);

    // 3) attention (bf16 QK + bf16 PV flash; K/V preconverted)
    attn_kernel<<<dim3(LQ / 128, Bz * Hh), 256>>>(
        qkv, kvb, kvb + (size_t)MROWS * Cc, attn);

    // 4) self-attn out proj + residual + LN(ln2) -> t1, and qk2 = t1 + qpos
    gemm_tc<256,64,64,3><<<dim3(4, 64), 256, SMEMB(64,64,3)>>>(
        attn, nullptr, sa_w, sa_b, tmp, MROWS, Cc, 0, 0,
        nullptr, nullptr, nullptr, 0, 256, 256, nullptr);
    add_ln_kernel<<<MROWS, 256>>>(tgt, tmp, ln2_g, ln2_b, qpos, t1, qk2);

    // 5+6) offsets + attention weights in one z-batched launch
    gemm_tc<256,64,64,3><<<dim3(4, 64, 2), 256, SMEMB(64,64,3)>>>(
        qk2, nullptr, off_w, off_b, off, MROWS, Cc, 0, 2,
        aw_w, aw_b, aw, 128, 256, 256, nullptr);

    // join value projection, then deformable sampling
    cudaStreamWaitEvent(0, evJoin, 0);
    deform_kernel<<<(MROWS * Hh) / 4, 128>>>(valb, off, aw, refp, attn);

    // 8) co proj + residual + LN(ln1) -> t2
    gemm_tc<256,64,64,3><<<dim3(4, 64), 256, SMEMB(64,64,3)>>>(
        attn, nullptr, co_w, co_b, tmp, MROWS, Cc, 0, 0,
        nullptr, nullptr, nullptr, 0, 256, 256, nullptr);
    add_ln_kernel<<<MROWS, 256>>>(t1, tmp, ln1_g, ln1_b, nullptr, t2, nullptr);

    // 9) FFN: f1 (relu), f2 split-K over z=4, fused reduce+LN
    gemm_tc<256,128,64,3><<<dim3(16, 32), 256, SMEMB(128,64,3)>>>(
        t2, nullptr, f1_w, f1_b, ffn, MROWS, DFF, 1, 0,
        nullptr, nullptr, nullptr, 0, 256, 256, nullptr);
    gemm_tc<256,64,64,3><<<dim3(4, 64, 4), 256, SMEMB(64,64,3)>>>(
        ffn, nullptr, f2_w, f2_b, part, MROWS, Cc, 0, 3,
        nullptr, zero, nullptr, 0, 1024, 1024, nullptr);
    add_ln4_kernel<<<MROWS, 256>>>(t2, part, ln3_g, ln3_b, out);
}